// round 15
// baseline (speedup 1.0000x reference)
#include <cuda_runtime.h>

#define NN 8192
#define EE 65536
#define GG 16
#define NELEM 10
#define CAP 32
#define NBY_PAD (NN + 32*NELEM)
#define NTILES (NBY_PAD/32)
#define OUTSZ (GG + NN*3)

typedef unsigned long long ull;

// ---------------- persistent device scratch (zero-init at load; self-cleaned) ----
__device__ float d_vec[EE*3];
__device__ float d_r[EE];
__device__ float d_Y[EE*16];
__device__ float d_Rb[EE*8];
__device__ float d_dRb[EE*8];
__device__ float d_A[NN*1024];
__device__ float d_Bf[NN*256];
__device__ float d_h1[NN*64];
__device__ float d_dh1[NN*64];
__device__ float d_dB1e[NELEM*256];
__device__ int   d_elem[NN];
__device__ int   d_deg[NN];            // zeroed by k_bwd0 each replay
__device__ int2  d_nbr[NN*CAP];        // (edge, sender)
__device__ int   d_elptr[NELEM+1];
__device__ int   d_nbyel[NBY_PAD];

#define BFLY(p) { _Pragma("unroll") for (int off = 16; off > 0; off >>= 1) p += __shfl_xor_sync(0xffffffffu, p, off); }
#define FFMA2(d,a,b,c) asm("fma.rn.f32x2 %0,%1,%2,%3;" : "=l"(d) : "l"(a), "l"(b), "l"(c))
__device__ __forceinline__ ull packf2(float lo, float hi){
  ull r; asm("mov.b64 %0,{%1,%2};" : "=l"(r) : "f"(lo), "f"(hi)); return r;
}
__device__ __forceinline__ void unpackf2(ull v, float& lo, float& hi){
  asm("mov.b64 {%0,%1},%2;" : "=f"(lo), "=f"(hi) : "l"(v));
}

// ------- geometry + nbr-list append ; elem / out-zero / h1-zero (extra blocks) -----
__global__ void k_geom(const float* __restrict__ pos, const float* __restrict__ shifts,
                       const int* __restrict__ ei, const float* __restrict__ attrs,
                       float* __restrict__ out){
  if (blockIdx.x >= 256){
    int i = (blockIdx.x - 256)*256 + threadIdx.x;   // 512 extra blocks: i < 131072
    ((float4*)d_h1)[i] = make_float4(0.f,0.f,0.f,0.f);
    if (i < OUTSZ) out[i] = 0.f;
    if (i < NN){
      int el = 0;
      const float* a = attrs + i*NELEM;
      #pragma unroll
      for (int e = 1; e < NELEM; e++) if (a[e] > 0.5f) el = e;
      d_elem[i] = el;
    }
    return;
  }
  int e = blockIdx.x*256 + threadIdx.x;
  int s = ei[e], n = ei[EE+e];
  float vx = pos[3*n]   - pos[3*s]   + shifts[3*e];
  float vy = pos[3*n+1] - pos[3*s+1] + shifts[3*e+1];
  float vz = pos[3*n+2] - pos[3*s+2] + shifts[3*e+2];
  float r = sqrtf(vx*vx + vy*vy + vz*vz + 1e-9f);
  float u = r*0.2f;
  if (u >= 1.f) return;
  int slot = atomicAdd(&d_deg[n], 1);
  if (slot < CAP) d_nbr[n*CAP + slot] = make_int2(e, s);
  float inv = 1.f/r;
  float x = vx*inv, y = vy*inv, z = vz*inv;
  d_vec[3*e] = x; d_vec[3*e+1] = y; d_vec[3*e+2] = z;
  d_r[e] = inv;
  float x2 = x*x, y2 = y*y, z2 = z*z;
  float* Y = d_Y + e*16;
  Y[0]  = 0.28209479177387814f;
  Y[1]  = 0.4886025119029199f*y;
  Y[2]  = 0.4886025119029199f*z;
  Y[3]  = 0.4886025119029199f*x;
  Y[4]  = 1.0925484305920792f*x*y;
  Y[5]  = 1.0925484305920792f*y*z;
  Y[6]  = 0.31539156525252005f*(3.f*z2 - 1.f);
  Y[7]  = 1.0925484305920792f*x*z;
  Y[8]  = 0.5462742152960396f*(x2 - y2);
  Y[9]  = 0.5900435899266435f*y*(3.f*x2 - y2);
  Y[10] = 2.890611442640554f*x*y*z;
  Y[11] = 0.4570457994644658f*y*(5.f*z2 - 1.f);
  Y[12] = 0.3731763325901154f*z*(5.f*z2 - 3.f);
  Y[13] = 0.4570457994644658f*x*(5.f*z2 - 1.f);
  Y[14] = 1.445305721320277f*z*(x2 - y2);
  Y[15] = 0.5900435899266435f*x*(x2 - 3.f*y2);
  float u2 = u*u; float u4 = u2*u2;
  float omu = 1.f - u;
  float cut  = 1.f + u4*u*(-21.f + u*(35.f - 15.f*u));
  float cutp = -105.f*u4*omu*omu;
  const float pref = 0.6324555320336759f;
  const float PI_F = 3.14159265358979323846f;
  float* R = d_Rb + e*8;
  float* D = d_dRb + e*8;
  #pragma unroll
  for (int b = 1; b <= 8; b++){
    float sp, cp;
    sincospif((float)b*u, &sp, &cp);
    R[b-1] = pref*sp*inv*cut;
    D[b-1] = pref*(((float)b*PI_F*0.2f)*cp*inv - sp*inv*inv)*cut
           + pref*sp*inv*cutp*0.2f;
  }
}

// ---------------- misc: element grouping (block 0) + dB1e (blocks 1..NELEM) ------
__global__ void k_misc(const float* __restrict__ attrs, const float* __restrict__ Wprod,
                       const float* __restrict__ w_read){
  if (blockIdx.x == 0){
    __shared__ int hist[NELEM], curs[NELEM];
    int tid = threadIdx.x;
    if (tid < NELEM) hist[tid] = 0;
    __syncthreads();
    int els[32];
    #pragma unroll
    for (int q = 0; q < 32; q++){
      int node = q*256 + tid;
      const float* a = attrs + node*NELEM;
      int el = 0;
      #pragma unroll
      for (int e = 1; e < NELEM; e++) if (a[e] > 0.5f) el = e;
      els[q] = el;
      atomicAdd(&hist[el], 1);
    }
    __syncthreads();
    if (tid == 0){
      int b = 0;
      #pragma unroll
      for (int e = 0; e < NELEM; e++){
        d_elptr[e] = b; curs[e] = b;
        b += (hist[e] + 31) & ~31;
      }
      d_elptr[NELEM] = b;
    }
    for (int i = tid; i < NBY_PAD; i += 256) d_nbyel[i] = -1;
    __syncthreads();
    #pragma unroll
    for (int q = 0; q < 32; q++){
      int p = atomicAdd(&curs[els[q]], 1);
      d_nbyel[p] = q*256 + tid;
    }
  } else {
    __shared__ float wr[64];
    int el = blockIdx.x - 1, f = threadIdx.x;
    if (f < 64) wr[f] = w_read[f];
    __syncthreads();
    const float* W = Wprod + (NELEM + el)*16384 + f*64;
    float acc = 0.f;
    #pragma unroll
    for (int c = 0; c < 64; c++) acc += wr[c]*W[c];
    d_dB1e[el*256 + f] = acc;
  }
}

// ======== staged forward gather over nbr list ========
template<int LAYER>
__device__ __forceinline__ void gather_core(
    int n, int lane, int dg, const float* __restrict__ Wemb,
    const float wr0[8], const float wr1[8],
    float a0[16], float a1[16])
{
  const unsigned FM = 0xffffffffu;
  for (int base = 0; base < dg; base += 32){
    int j = base + lane;
    int jj = (j < dg) ? j : 0;
    int2 es = d_nbr[n*CAP + jj];
    int e = es.x, s = es.y;
    int els = (LAYER == 0) ? d_elem[s] : 0;
    float4 R0 = *(const float4*)(d_Rb + e*8);
    float4 R1 = *(const float4*)(d_Rb + e*8 + 4);
    const float4* Yp = (const float4*)(d_Y + e*16);
    float4 Y0 = Yp[0], Y1 = Yp[1], Y2 = Yp[2], Y3 = Yp[3];
    int m = min(32, dg - base);
    for (int k = 0; k < m; k++){
      int sk = __shfl_sync(FM, s, k);
      float hv0, hv1;
      if (LAYER == 0){
        int elk = __shfl_sync(FM, els, k);
        hv0 = Wemb[elk*64 + lane]; hv1 = Wemb[elk*64 + 32 + lane];
      } else {
        hv0 = d_h1[sk*64 + lane]; hv1 = d_h1[sk*64 + 32 + lane];
      }
      float rb, w0, w1;
      rb = __shfl_sync(FM, R0.x, k); w0  = rb*wr0[0]; w1  = rb*wr1[0];
      rb = __shfl_sync(FM, R0.y, k); w0 += rb*wr0[1]; w1 += rb*wr1[1];
      rb = __shfl_sync(FM, R0.z, k); w0 += rb*wr0[2]; w1 += rb*wr1[2];
      rb = __shfl_sync(FM, R0.w, k); w0 += rb*wr0[3]; w1 += rb*wr1[3];
      rb = __shfl_sync(FM, R1.x, k); w0 += rb*wr0[4]; w1 += rb*wr1[4];
      rb = __shfl_sync(FM, R1.y, k); w0 += rb*wr0[5]; w1 += rb*wr1[5];
      rb = __shfl_sync(FM, R1.z, k); w0 += rb*wr0[6]; w1 += rb*wr1[6];
      rb = __shfl_sync(FM, R1.w, k); w0 += rb*wr0[7]; w1 += rb*wr1[7];
      float wh0 = w0*hv0, wh1 = w1*hv1;
      float yk;
      yk = __shfl_sync(FM, Y0.x, k); a0[0]  += wh0*yk; a1[0]  += wh1*yk;
      yk = __shfl_sync(FM, Y0.y, k); a0[1]  += wh0*yk; a1[1]  += wh1*yk;
      yk = __shfl_sync(FM, Y0.z, k); a0[2]  += wh0*yk; a1[2]  += wh1*yk;
      yk = __shfl_sync(FM, Y0.w, k); a0[3]  += wh0*yk; a1[3]  += wh1*yk;
      yk = __shfl_sync(FM, Y1.x, k); a0[4]  += wh0*yk; a1[4]  += wh1*yk;
      yk = __shfl_sync(FM, Y1.y, k); a0[5]  += wh0*yk; a1[5]  += wh1*yk;
      yk = __shfl_sync(FM, Y1.z, k); a0[6]  += wh0*yk; a1[6]  += wh1*yk;
      yk = __shfl_sync(FM, Y1.w, k); a0[7]  += wh0*yk; a1[7]  += wh1*yk;
      yk = __shfl_sync(FM, Y2.x, k); a0[8]  += wh0*yk; a1[8]  += wh1*yk;
      yk = __shfl_sync(FM, Y2.y, k); a0[9]  += wh0*yk; a1[9]  += wh1*yk;
      yk = __shfl_sync(FM, Y2.z, k); a0[10] += wh0*yk; a1[10] += wh1*yk;
      yk = __shfl_sync(FM, Y2.w, k); a0[11] += wh0*yk; a1[11] += wh1*yk;
      yk = __shfl_sync(FM, Y3.x, k); a0[12] += wh0*yk; a1[12] += wh1*yk;
      yk = __shfl_sync(FM, Y3.y, k); a0[13] += wh0*yk; a1[13] += wh1*yk;
      yk = __shfl_sync(FM, Y3.z, k); a0[14] += wh0*yk; a1[14] += wh1*yk;
      yk = __shfl_sync(FM, Y3.w, k); a0[15] += wh0*yk; a1[15] += wh1*yk;
    }
  }
}

// ---------------- gather layer 0: A (float2 pairs) + B ----------------
__global__ void k_gather0(const float* __restrict__ Wemb, const float* __restrict__ Wrad){
  int n = blockIdx.x*4 + (threadIdx.x >> 5);
  int lane = threadIdx.x & 31;
  float wr0[8], wr1[8];
  #pragma unroll
  for (int b = 0; b < 8; b++){ wr0[b] = Wrad[b*64+lane]; wr1[b] = Wrad[b*64+32+lane]; }
#if __CUDA_ARCH__ >= 900
  cudaGridDependencySynchronize();
#endif
  float a0[16], a1[16];
  #pragma unroll
  for (int i = 0; i < 16; i++){ a0[i] = 0.f; a1[i] = 0.f; }
  int dg = min(d_deg[n], CAP);
  gather_core<0>(n, lane, dg, Wemb, wr0, wr1, a0, a1);
  float2* A2 = (float2*)(d_A + n*1024);
  #pragma unroll
  for (int lm = 0; lm < 16; lm++) A2[lm*32 + lane] = make_float2(a0[lm], a1[lm]);
  float b0[4] = {0,0,0,0}, b1[4] = {0,0,0,0};
  #pragma unroll
  for (int lm = 0; lm < 16; lm++){
    int l = (lm == 0) ? 0 : (lm < 4) ? 1 : (lm < 9) ? 2 : 3;
    b0[l] += a0[lm]*a0[lm]; b1[l] += a1[lm]*a1[lm];
  }
  #pragma unroll
  for (int l = 0; l < 4; l++){
    d_Bf[n*256 + l*64 + lane]      = b0[l];
    d_Bf[n*256 + l*64 + 32 + lane] = b1[l];
  }
}

// ---------------- staged per-edge backward core; forces -> out ----------------
template<int LAYER>
__device__ __forceinline__ void edge_bwd_loop(
    int n, int lane, int dg, const float* __restrict__ Wemb,
    const float dA0[16], const float dA1[16],
    const float wr0[8], const float wr1[8],
    float* __restrict__ fout)
{
  const unsigned FM = 0xffffffffu;
  float accx = 0.f, accy = 0.f, accz = 0.f;
  const float c1 = 0.4886025119029199f;
  for (int base = 0; base < dg; base += 32){
    int j = base + lane;
    int jj = (j < dg) ? j : 0;
    int2 es = d_nbr[n*CAP + jj];
    int e = es.x, s = es.y;
    int els = (LAYER == 0) ? d_elem[s] : 0;
    float4 R0 = *(const float4*)(d_Rb + e*8);
    float4 R1 = *(const float4*)(d_Rb + e*8 + 4);
    float4 D0 = *(const float4*)(d_dRb + e*8);
    float4 D1 = *(const float4*)(d_dRb + e*8 + 4);
    const float4* Yp = (const float4*)(d_Y + e*16);
    float4 Y0 = Yp[0], Y1 = Yp[1], Y2 = Yp[2], Y3 = Yp[3];
    float vx = d_vec[3*e], vy = d_vec[3*e+1], vz = d_vec[3*e+2];
    float vi = d_r[e];
    int m = min(32, dg - base);
    for (int k = 0; k < m; k++){
      int sk = __shfl_sync(FM, s, k);
      float hv0, hv1;
      if (LAYER == 1){
        hv0 = d_h1[sk*64 + lane]; hv1 = d_h1[sk*64 + 32 + lane];
      } else {
        int elk = __shfl_sync(FM, els, k);
        hv0 = Wemb[elk*64 + lane]; hv1 = Wemb[elk*64 + 32 + lane];
      }
      float rb, db, w0, w1, s0, s1;
      rb = __shfl_sync(FM, R0.x, k); w0  = rb*wr0[0]; w1  = rb*wr1[0];
      rb = __shfl_sync(FM, R0.y, k); w0 += rb*wr0[1]; w1 += rb*wr1[1];
      rb = __shfl_sync(FM, R0.z, k); w0 += rb*wr0[2]; w1 += rb*wr1[2];
      rb = __shfl_sync(FM, R0.w, k); w0 += rb*wr0[3]; w1 += rb*wr1[3];
      rb = __shfl_sync(FM, R1.x, k); w0 += rb*wr0[4]; w1 += rb*wr1[4];
      rb = __shfl_sync(FM, R1.y, k); w0 += rb*wr0[5]; w1 += rb*wr1[5];
      rb = __shfl_sync(FM, R1.z, k); w0 += rb*wr0[6]; w1 += rb*wr1[6];
      rb = __shfl_sync(FM, R1.w, k); w0 += rb*wr0[7]; w1 += rb*wr1[7];
      db = __shfl_sync(FM, D0.x, k); s0  = db*wr0[0]; s1  = db*wr1[0];
      db = __shfl_sync(FM, D0.y, k); s0 += db*wr0[1]; s1 += db*wr1[1];
      db = __shfl_sync(FM, D0.z, k); s0 += db*wr0[2]; s1 += db*wr1[2];
      db = __shfl_sync(FM, D0.w, k); s0 += db*wr0[3]; s1 += db*wr1[3];
      db = __shfl_sync(FM, D1.x, k); s0 += db*wr0[4]; s1 += db*wr1[4];
      db = __shfl_sync(FM, D1.y, k); s0 += db*wr0[5]; s1 += db*wr1[5];
      db = __shfl_sync(FM, D1.z, k); s0 += db*wr0[6]; s1 += db*wr1[6];
      db = __shfl_sync(FM, D1.w, k); s0 += db*wr0[7]; s1 += db*wr1[7];
      float Yv[16];
      Yv[0]  = __shfl_sync(FM, Y0.x, k); Yv[1]  = __shfl_sync(FM, Y0.y, k);
      Yv[2]  = __shfl_sync(FM, Y0.z, k); Yv[3]  = __shfl_sync(FM, Y0.w, k);
      Yv[4]  = __shfl_sync(FM, Y1.x, k); Yv[5]  = __shfl_sync(FM, Y1.y, k);
      Yv[6]  = __shfl_sync(FM, Y1.z, k); Yv[7]  = __shfl_sync(FM, Y1.w, k);
      Yv[8]  = __shfl_sync(FM, Y2.x, k); Yv[9]  = __shfl_sync(FM, Y2.y, k);
      Yv[10] = __shfl_sync(FM, Y2.z, k); Yv[11] = __shfl_sync(FM, Y2.w, k);
      Yv[12] = __shfl_sync(FM, Y3.x, k); Yv[13] = __shfl_sync(FM, Y3.y, k);
      Yv[14] = __shfl_sync(FM, Y3.z, k); Yv[15] = __shfl_sync(FM, Y3.w, k);
      float x = __shfl_sync(FM, vx, k);
      float y = __shfl_sync(FM, vy, k);
      float z = __shfl_sync(FM, vz, k);
      float inv = __shfl_sync(FM, vi, k);
      float g0 = 0.f, g1 = 0.f;
      #pragma unroll
      for (int lm = 0; lm < 16; lm++){ g0 += dA0[lm]*Yv[lm]; g1 += dA1[lm]*Yv[lm]; }
      float wh0 = w0*hv0, wh1 = w1*hv1;
      float x2my2 = x*x - y*y;
      float z2 = z*z;
      float c4x = 1.0925484305920792f*x, c4y = 1.0925484305920792f*y, c4z = 1.0925484305920792f*z;
      float txy = 2.890611442640554f*x*y, txz = 2.890611442640554f*x*z, tyz = 2.890611442640554f*y*z;
      float q13 = 0.4570457994644658f*(5.f*z2 - 1.f);
      float e9  = 3.540261539559861f*x*y;
      float e15 = 1.7701307697799304f*x2my2;
      float pz6 = 1.8923493915151203f*z;
      float q11y = 4.570457994644658f*y*z, q11x = 4.570457994644658f*x*z;
      float p12 = 0.3731763325901154f*(15.f*z2 - 3.f);
      float p14 = 1.445305721320277f*x2my2;
      float px0 = c1*dA0[3] + c4y*dA0[4] + c4z*dA0[7] + c4x*dA0[8] + e9*dA0[9]
                + tyz*dA0[10] + q13*dA0[13] + txz*dA0[14] + e15*dA0[15];
      float py0 = c1*dA0[1] + c4x*dA0[4] + c4z*dA0[5] - c4y*dA0[8] + e15*dA0[9]
                + txz*dA0[10] + q13*dA0[11] - tyz*dA0[14] - e9*dA0[15];
      float pz0 = c1*dA0[2] + c4y*dA0[5] + pz6*dA0[6] + c4x*dA0[7] + txy*dA0[10]
                + q11y*dA0[11] + p12*dA0[12] + q11x*dA0[13] + p14*dA0[14];
      float px1 = c1*dA1[3] + c4y*dA1[4] + c4z*dA1[7] + c4x*dA1[8] + e9*dA1[9]
                + tyz*dA1[10] + q13*dA1[13] + txz*dA1[14] + e15*dA1[15];
      float py1 = c1*dA1[1] + c4x*dA1[4] + c4z*dA1[5] - c4y*dA1[8] + e15*dA1[9]
                + txz*dA1[10] + q13*dA1[11] - tyz*dA1[14] - e9*dA1[15];
      float pz1 = c1*dA1[2] + c4y*dA1[5] + pz6*dA1[6] + c4x*dA1[7] + txy*dA1[10]
                + q11y*dA1[11] + p12*dA1[12] + q11x*dA1[13] + p14*dA1[14];
      float pgx = wh0*px0 + wh1*px1;
      float pgy = wh0*py0 + wh1*py1;
      float pgz = wh0*pz0 + wh1*pz1;
      float prad = g0*hv0*s0 + g1*hv1*s1;
      BFLY(pgx); BFLY(pgy); BFLY(pgz); BFLY(prad);
      if (lane == 0){
        float gdotu = pgx*x + pgy*y + pgz*z;
        float dvx = inv*(pgx - gdotu*x) + prad*x;
        float dvy = inv*(pgy - gdotu*y) + prad*y;
        float dvz = inv*(pgz - gdotu*z) + prad*z;
        accx += dvx; accy += dvy; accz += dvz;
        atomicAdd(&fout[3*sk],   dvx);
        atomicAdd(&fout[3*sk+1], dvy);
        atomicAdd(&fout[3*sk+2], dvz);
      }
      if (LAYER == 1){
        atomicAdd(&d_dh1[sk*64 + lane],      g0*w0);
        atomicAdd(&d_dh1[sk*64 + 32 + lane], g1*w1);
      }
    }
  }
  if (lane == 0 && dg > 0){
    atomicAdd(&fout[3*n],   -accx);
    atomicAdd(&fout[3*n+1], -accy);
    atomicAdd(&fout[3*n+2], -accz);
  }
}

// ---------------- fused layer-1 gather (B) + layer-1 backward ----------------
__global__ void k_gfused1(const float* __restrict__ Wemb, const float* __restrict__ Wrad,
                          float* __restrict__ out){
  int n = blockIdx.x*4 + (threadIdx.x >> 5);
  int lane = threadIdx.x & 31;
  float wr0[8], wr1[8];
  #pragma unroll
  for (int b = 0; b < 8; b++){ wr0[b] = Wrad[b*64+lane]; wr1[b] = Wrad[b*64+32+lane]; }
#if __CUDA_ARCH__ >= 900
  cudaGridDependencySynchronize();
#endif
  float a0[16], a1[16];
  #pragma unroll
  for (int i = 0; i < 16; i++){ a0[i] = 0.f; a1[i] = 0.f; }
  int dg = min(d_deg[n], CAP);
  gather_core<1>(n, lane, dg, Wemb, wr0, wr1, a0, a1);
  float b0[4] = {0,0,0,0}, b1[4] = {0,0,0,0};
  #pragma unroll
  for (int lm = 0; lm < 16; lm++){
    int l = (lm == 0) ? 0 : (lm < 4) ? 1 : (lm < 9) ? 2 : 3;
    b0[l] += a0[lm]*a0[lm]; b1[l] += a1[lm]*a1[lm];
  }
  #pragma unroll
  for (int l = 0; l < 4; l++){
    d_Bf[n*256 + l*64 + lane]      = b0[l];
    d_Bf[n*256 + l*64 + 32 + lane] = b1[l];
  }
  if (dg == 0) return;
  const float* dB = d_dB1e + d_elem[n]*256;
  #pragma unroll
  for (int lm = 0; lm < 16; lm++){
    int l = (lm == 0) ? 0 : (lm < 4) ? 1 : (lm < 9) ? 2 : 3;
    a0[lm] = 2.f*a0[lm]*dB[l*64 + lane];
    a1[lm] = 2.f*a1[lm]*dB[l*64 + 32 + lane];
  }
  edge_bwd_loop<1>(n, lane, dg, Wemb, a0, a1, wr0, wr1, out + GG);
}

// --- K-split warp-per-4-nodes GEMM: B in regs, 32KB weight chunk, shfl broadcast ---
// grid (NTILES, 2), 256 threads; chunk owns f in [chunk*128, chunk*128+128)
#define GH_SMEM (8192*4 + GG*4 + 32*4 + 128)
template<int LAYER>
__global__ void __launch_bounds__(256, 3)
k_gemm_h(const float* __restrict__ Wprod, const float* __restrict__ w_read,
         const float* __restrict__ ae, const int* __restrict__ batch,
         float* __restrict__ out){
  extern __shared__ float sm[];
  float* Ws = sm;                        // [128 f][64 c]
  float* engs = sm + 8192;               // [16]
  int* nids = (int*)(engs + GG);         // [32]
  int base = blockIdx.x*32;
  if (base >= d_elptr[NELEM]) return;
  int chunk = blockIdx.y;
  int el = 0;
  #pragma unroll
  for (int e = 1; e < NELEM; e++) if (d_elptr[e] <= base) el = e;
  int tid = threadIdx.x;                 // 256
  const float4* W4 = (const float4*)(Wprod + (LAYER*NELEM + el)*16384 + chunk*8192);
  float4* Ws4 = (float4*)Ws;
  #pragma unroll
  for (int i = 0; i < 8; i++) Ws4[tid + i*256] = W4[tid + i*256];
  if (tid < 32) nids[tid] = d_nbyel[base + tid];
  if (LAYER == 1 && tid < GG) engs[tid] = 0.f;
  __syncthreads();
#if __CUDA_ARCH__ >= 900
  cudaGridDependencySynchronize();      // weight-load prologue overlapped with producer
#endif
  const unsigned FM = 0xffffffffu;
  int w = tid >> 5, lane = tid & 31;
  int nn[4];
  float Br0[4], Br1[4], Br2[4], Br3[4];
  #pragma unroll
  for (int i = 0; i < 4; i++) nn[i] = nids[4*w + i];
  {
    const float* B0p = d_Bf + (nn[0] >= 0 ? nn[0] : 0)*256 + chunk*128;
    const float* B1p = d_Bf + (nn[1] >= 0 ? nn[1] : 0)*256 + chunk*128;
    const float* B2p = d_Bf + (nn[2] >= 0 ? nn[2] : 0)*256 + chunk*128;
    const float* B3p = d_Bf + (nn[3] >= 0 ? nn[3] : 0)*256 + chunk*128;
    #pragma unroll
    for (int q = 0; q < 4; q++){
      Br0[q] = (nn[0] >= 0) ? B0p[q*32 + lane] : 0.f;
      Br1[q] = (nn[1] >= 0) ? B1p[q*32 + lane] : 0.f;
      Br2[q] = (nn[2] >= 0) ? B2p[q*32 + lane] : 0.f;
      Br3[q] = (nn[3] >= 0) ? B3p[q*32 + lane] : 0.f;
    }
  }
  const ull* Wsu = (const ull*)Ws;       // [128 f][32 channel-pairs]
  ull acc0 = 0, acc1 = 0, acc2 = 0, acc3 = 0;
  #pragma unroll
  for (int q = 0; q < 4; q++){
    #pragma unroll
    for (int kk = 0; kk < 32; kk += 2){
      float b0a = __shfl_sync(FM, Br0[q], kk), b0b = __shfl_sync(FM, Br0[q], kk+1);
      float b1a = __shfl_sync(FM, Br1[q], kk), b1b = __shfl_sync(FM, Br1[q], kk+1);
      float b2a = __shfl_sync(FM, Br2[q], kk), b2b = __shfl_sync(FM, Br2[q], kk+1);
      float b3a = __shfl_sync(FM, Br3[q], kk), b3b = __shfl_sync(FM, Br3[q], kk+1);
      ull wva = Wsu[(q*32 + kk)*32 + lane];
      ull wvb = Wsu[(q*32 + kk + 1)*32 + lane];
      FFMA2(acc0, packf2(b0a, b0a), wva, acc0);
      FFMA2(acc1, packf2(b1a, b1a), wva, acc1);
      FFMA2(acc2, packf2(b2a, b2a), wva, acc2);
      FFMA2(acc3, packf2(b3a, b3a), wva, acc3);
      FFMA2(acc0, packf2(b0b, b0b), wvb, acc0);
      FFMA2(acc1, packf2(b1b, b1b), wvb, acc1);
      FFMA2(acc2, packf2(b2b, b2b), wvb, acc2);
      FFMA2(acc3, packf2(b3b, b3b), wvb, acc3);
    }
  }
  if (LAYER == 0){
    #pragma unroll
    for (int i = 0; i < 4; i++){
      ull a = (i == 0) ? acc0 : (i == 1) ? acc1 : (i == 2) ? acc2 : acc3;
      if (nn[i] >= 0){
        float lo, hi; unpackf2(a, lo, hi);
        atomicAdd(&d_h1[nn[i]*64 + 2*lane],     lo);
        atomicAdd(&d_h1[nn[i]*64 + 2*lane + 1], hi);
      }
    }
  } else {
    float wlo = w_read[2*lane], whi = w_read[2*lane + 1];
    #pragma unroll
    for (int i = 0; i < 4; i++){
      ull a = (i == 0) ? acc0 : (i == 1) ? acc1 : (i == 2) ? acc2 : acc3;
      float lo, hi; unpackf2(a, lo, hi);
      float p = lo*wlo + hi*whi;
      BFLY(p);
      if (lane == 0 && nn[i] >= 0)
        atomicAdd(&engs[batch[nn[i]]], p + ((chunk == 0) ? ae[el] : 0.f));
    }
    __syncthreads();
    if (tid < GG){
      float v = engs[tid];
      if (v != 0.f) atomicAdd(&out[tid], v);
    }
  }
}

// ------ fused: dB0 tile + layer-0 backward; 512 threads (16 warps x 2 nodes) -------
#define BWD0_SMEM (64*264*4 + 32*66*4 + 32*256*4 + 128)
__global__ void __launch_bounds__(512, 2)
k_bwd0(const float* __restrict__ Wprod, const float* __restrict__ Wemb,
       const float* __restrict__ Wrad, float* __restrict__ out){
  extern __shared__ float sm[];
  float* Wt  = sm;                        // [c][f] 64 x 264
  float* dhs = sm + 64*264;               // [node][c] 32 x 66
  float* dBs = sm + 64*264 + 32*66;       // [node][f] 32 x 256
  int* nids  = (int*)(sm + 64*264 + 32*66 + 32*256);
  int base = blockIdx.x*32;
  if (base >= d_elptr[NELEM]) return;
  int el = 0;
  #pragma unroll
  for (int e = 1; e < NELEM; e++) if (d_elptr[e] <= base) el = e;
  int tid = threadIdx.x;   // 512
  const float* W = Wprod + el*16384;
  for (int i = tid; i < 16384; i += 512){
    int f = i >> 6, c = i & 63;
    Wt[c*264 + f] = W[i];
  }
  if (tid < 32) nids[tid] = d_nbyel[base + tid];
  __syncthreads();
#if __CUDA_ARCH__ >= 900
  cudaGridDependencySynchronize();      // weight-load prologue overlapped with gfused1
#endif
  for (int i = tid; i < 32*64; i += 512){
    int k = i >> 6, c = i & 63;
    int nn = nids[k];
    if (nn >= 0){
      dhs[k*66 + c] = d_dh1[nn*64 + c];
      d_dh1[nn*64 + c] = 0.f;             // self-clean for next replay
    } else {
      dhs[k*66 + c] = 0.f;
    }
  }
  __syncthreads();
  {
    // 512 threads: node ng = tid>>4 (32 nodes), f-group fg = tid&15 (16 f each)
    int ng = tid >> 4, fg = tid & 15;
    float acc[16];
    #pragma unroll
    for (int i = 0; i < 16; i++) acc[i] = 0.f;
    #pragma unroll 2
    for (int c = 0; c < 64; c++){
      float dd = dhs[ng*66 + c];
      const float4* Wc = (const float4*)(Wt + c*264 + fg*16);
      #pragma unroll
      for (int q = 0; q < 4; q++){
        float4 w = Wc[q];
        acc[4*q]   += dd*w.x; acc[4*q+1] += dd*w.y; acc[4*q+2] += dd*w.z; acc[4*q+3] += dd*w.w;
      }
    }
    float4* o = (float4*)(dBs + ng*256 + fg*16);
    #pragma unroll
    for (int q = 0; q < 4; q++) o[q] = make_float4(acc[4*q],acc[4*q+1],acc[4*q+2],acc[4*q+3]);
  }
  __syncthreads();
  int w = tid >> 5, lane = tid & 31;     // 16 warps x 2 nodes
  float wr0[8], wr1[8];
  #pragma unroll
  for (int b = 0; b < 8; b++){ wr0[b] = Wrad[b*64+lane]; wr1[b] = Wrad[b*64+32+lane]; }
  for (int q = 0; q < 2; q++){
    int nloc = w*2 + q;
    int nn = nids[nloc];
    if (nn < 0) continue;
    int dg = min(d_deg[nn], CAP);
    if (lane == 0) d_deg[nn] = 0;         // self-clean for next replay
    if (dg == 0) continue;
    const float* dB = dBs + nloc*256;
    const float2* A2 = (const float2*)(d_A + nn*1024);
    float dA0[16], dA1[16];
    #pragma unroll
    for (int lm = 0; lm < 16; lm++){
      int l = (lm == 0) ? 0 : (lm < 4) ? 1 : (lm < 9) ? 2 : 3;
      float2 av = A2[lm*32 + lane];
      dA0[lm] = 2.f*av.x*dB[l*64 + lane];
      dA1[lm] = 2.f*av.y*dB[l*64 + 32 + lane];
    }
    edge_bwd_loop<0>(nn, lane, dg, Wemb, dA0, dA1, wr0, wr1, out + GG);
  }
}

// ---------------- launch ----------------
extern "C" void kernel_launch(void* const* d_in, const int* in_sizes, int n_in,
                              void* d_out, int out_size){
  const float* pos    = (const float*)d_in[0];
  const float* attrs  = (const float*)d_in[1];
  const float* shifts = (const float*)d_in[2];
  const float* Wemb   = (const float*)d_in[3];
  const float* aew    = (const float*)d_in[4];
  const float* Wrad   = (const float*)d_in[5];
  const float* Wprod  = (const float*)d_in[6];
  const float* wread  = (const float*)d_in[7];
  const int*   ei     = (const int*)d_in[8];
  const int*   batch  = (const int*)d_in[9];
  float* out = (float*)d_out;

  static cudaStream_t s2 = nullptr;
  static cudaEvent_t ev0 = nullptr, evM = nullptr, ev1 = nullptr, ev2 = nullptr;
  if (!s2){
    cudaFuncSetAttribute(k_gemm_h<0>, cudaFuncAttributeMaxDynamicSharedMemorySize, GH_SMEM);
    cudaFuncSetAttribute(k_gemm_h<1>, cudaFuncAttributeMaxDynamicSharedMemorySize, GH_SMEM);
    cudaFuncSetAttribute(k_bwd0,      cudaFuncAttributeMaxDynamicSharedMemorySize, BWD0_SMEM);
    cudaStreamCreateWithFlags(&s2, cudaStreamNonBlocking);
    cudaEventCreateWithFlags(&ev0, cudaEventDisableTiming);
    cudaEventCreateWithFlags(&evM, cudaEventDisableTiming);
    cudaEventCreateWithFlags(&ev1, cudaEventDisableTiming);
    cudaEventCreateWithFlags(&ev2, cudaEventDisableTiming);
  }

  // fork misc (element grouping + dB1e) — depends only on inputs
  cudaEventRecord(ev0, 0);
  cudaStreamWaitEvent(s2, ev0, 0);
  k_misc<<<1 + NELEM, 256, 0, s2>>>(attrs, Wprod, wread);
  cudaEventRecord(evM, s2);

  k_geom<<<256 + 512, 256>>>(pos, shifts, ei, attrs, out);

  cudaLaunchAttribute pdl[1];
  pdl[0].id = cudaLaunchAttributeProgrammaticStreamSerialization;
  pdl[0].val.programmaticStreamSerializationAllowed = 1;

  {
    cudaLaunchConfig_t cfg = {};
    cfg.gridDim = dim3(NN/4); cfg.blockDim = dim3(128);
    cfg.dynamicSmemBytes = 0; cfg.stream = 0;
    cfg.attrs = pdl; cfg.numAttrs = 1;
    cudaLaunchKernelEx(&cfg, k_gather0, Wemb, Wrad);
  }
  cudaStreamWaitEvent(0, evM, 0);
  {
    cudaLaunchConfig_t cfg = {};
    cfg.gridDim = dim3(NTILES, 2); cfg.blockDim = dim3(256);
    cfg.dynamicSmemBytes = GH_SMEM; cfg.stream = 0;
    cfg.attrs = pdl; cfg.numAttrs = 1;
    cudaLaunchKernelEx(&cfg, k_gemm_h<0>, Wprod, wread, aew, batch, out);
  }
  {
    cudaLaunchConfig_t cfg = {};
    cfg.gridDim = dim3(NN/4); cfg.blockDim = dim3(128);
    cfg.dynamicSmemBytes = 0; cfg.stream = 0;
    cfg.attrs = pdl; cfg.numAttrs = 1;
    cudaLaunchKernelEx(&cfg, k_gfused1, Wemb, Wrad + 512, out);
  }

  // fork: energy GEMM (s2) concurrent with layer-0 backward (stream 0)
  cudaEventRecord(ev1, 0);
  cudaStreamWaitEvent(s2, ev1, 0);
  k_gemm_h<1><<<dim3(NTILES, 2), 256, GH_SMEM, s2>>>(Wprod, wread, aew, batch, out);
  cudaEventRecord(ev2, s2);

  {
    cudaLaunchConfig_t cfg = {};
    cfg.gridDim = dim3(NTILES); cfg.blockDim = dim3(512);
    cfg.dynamicSmemBytes = BWD0_SMEM; cfg.stream = 0;
    cfg.attrs = pdl; cfg.numAttrs = 1;
    cudaLaunchKernelEx(&cfg, k_bwd0, Wprod, Wemb, Wrad, out);
  }
  cudaStreamWaitEvent(0, ev2, 0);
}

// round 16
// speedup vs baseline: 1.4336x; 1.4336x over previous
#include <cuda_runtime.h>

#define NN 8192
#define EE 65536
#define GG 16
#define NELEM 10
#define CAP 32
#define NBY_PAD (NN + 32*NELEM)
#define NTILES (NBY_PAD/32)
#define NTILES16 (NBY_PAD/16)
#define OUTSZ (GG + NN*3)

typedef unsigned long long ull;

// ---------------- persistent device scratch (zero-init at load; self-cleaned) ----
__device__ float d_vec[EE*3];
__device__ float d_r[EE];
__device__ float d_Y[EE*16];
__device__ float d_Rb[EE*8];
__device__ float d_dRb[EE*8];
__device__ float d_A[NN*1024];
__device__ float d_Bf[NN*256];
__device__ float d_h1[NN*64];
__device__ float d_dh1[NN*64];
__device__ float d_dB1e[NELEM*256];
__device__ int   d_elem[NN];
__device__ int   d_deg[NN];            // zeroed by k_bwd0 each replay
__device__ int2  d_nbr[NN*CAP];        // (edge, sender)
__device__ int   d_elptr[NELEM+1];
__device__ int   d_nbyel[NBY_PAD];

#define BFLY(p) { _Pragma("unroll") for (int off = 16; off > 0; off >>= 1) p += __shfl_xor_sync(0xffffffffu, p, off); }
#define FFMA2(d,a,b,c) asm("fma.rn.f32x2 %0,%1,%2,%3;" : "=l"(d) : "l"(a), "l"(b), "l"(c))
__device__ __forceinline__ ull packf2(float lo, float hi){
  ull r; asm("mov.b64 %0,{%1,%2};" : "=l"(r) : "f"(lo), "f"(hi)); return r;
}
__device__ __forceinline__ void unpackf2(ull v, float& lo, float& hi){
  asm("mov.b64 {%0,%1},%2;" : "=f"(lo), "=f"(hi) : "l"(v));
}

// ---------------- geometry + nbr-list append ; elem / out-zero (rest) --------------
__global__ void k_geom(const float* __restrict__ pos, const float* __restrict__ shifts,
                       const int* __restrict__ ei, const float* __restrict__ attrs,
                       float* __restrict__ out){
  if (blockIdx.x >= 256){
    int i = (blockIdx.x - 256)*256 + threadIdx.x;
    if (i < OUTSZ) out[i] = 0.f;
    if (i < NN){
      int el = 0;
      const float* a = attrs + i*NELEM;
      #pragma unroll
      for (int e = 1; e < NELEM; e++) if (a[e] > 0.5f) el = e;
      d_elem[i] = el;
    }
    return;
  }
  int e = blockIdx.x*256 + threadIdx.x;
  int s = ei[e], n = ei[EE+e];
  float vx = pos[3*n]   - pos[3*s]   + shifts[3*e];
  float vy = pos[3*n+1] - pos[3*s+1] + shifts[3*e+1];
  float vz = pos[3*n+2] - pos[3*s+2] + shifts[3*e+2];
  float r = sqrtf(vx*vx + vy*vy + vz*vz + 1e-9f);
  float u = r*0.2f;
  if (u >= 1.f) return;
  int slot = atomicAdd(&d_deg[n], 1);
  if (slot < CAP) d_nbr[n*CAP + slot] = make_int2(e, s);
  float inv = 1.f/r;
  float x = vx*inv, y = vy*inv, z = vz*inv;
  d_vec[3*e] = x; d_vec[3*e+1] = y; d_vec[3*e+2] = z;
  d_r[e] = inv;
  float x2 = x*x, y2 = y*y, z2 = z*z;
  float* Y = d_Y + e*16;
  Y[0]  = 0.28209479177387814f;
  Y[1]  = 0.4886025119029199f*y;
  Y[2]  = 0.4886025119029199f*z;
  Y[3]  = 0.4886025119029199f*x;
  Y[4]  = 1.0925484305920792f*x*y;
  Y[5]  = 1.0925484305920792f*y*z;
  Y[6]  = 0.31539156525252005f*(3.f*z2 - 1.f);
  Y[7]  = 1.0925484305920792f*x*z;
  Y[8]  = 0.5462742152960396f*(x2 - y2);
  Y[9]  = 0.5900435899266435f*y*(3.f*x2 - y2);
  Y[10] = 2.890611442640554f*x*y*z;
  Y[11] = 0.4570457994644658f*y*(5.f*z2 - 1.f);
  Y[12] = 0.3731763325901154f*z*(5.f*z2 - 3.f);
  Y[13] = 0.4570457994644658f*x*(5.f*z2 - 1.f);
  Y[14] = 1.445305721320277f*z*(x2 - y2);
  Y[15] = 0.5900435899266435f*x*(x2 - 3.f*y2);
  float u2 = u*u; float u4 = u2*u2;
  float omu = 1.f - u;
  float cut  = 1.f + u4*u*(-21.f + u*(35.f - 15.f*u));
  float cutp = -105.f*u4*omu*omu;
  const float pref = 0.6324555320336759f;
  const float PI_F = 3.14159265358979323846f;
  float* R = d_Rb + e*8;
  float* D = d_dRb + e*8;
  #pragma unroll
  for (int b = 1; b <= 8; b++){
    float sp, cp;
    sincospif((float)b*u, &sp, &cp);
    R[b-1] = pref*sp*inv*cut;
    D[b-1] = pref*(((float)b*PI_F*0.2f)*cp*inv - sp*inv*inv)*cut
           + pref*sp*inv*cutp*0.2f;
  }
}

// ---------------- misc: element grouping (block 0) + dB1e (blocks 1..NELEM) ------
__global__ void k_misc(const float* __restrict__ attrs, const float* __restrict__ Wprod,
                       const float* __restrict__ w_read){
  if (blockIdx.x == 0){
    __shared__ int hist[NELEM], curs[NELEM];
    int tid = threadIdx.x;
    if (tid < NELEM) hist[tid] = 0;
    __syncthreads();
    int els[32];
    #pragma unroll
    for (int q = 0; q < 32; q++){
      int node = q*256 + tid;
      const float* a = attrs + node*NELEM;
      int el = 0;
      #pragma unroll
      for (int e = 1; e < NELEM; e++) if (a[e] > 0.5f) el = e;
      els[q] = el;
      atomicAdd(&hist[el], 1);
    }
    __syncthreads();
    if (tid == 0){
      int b = 0;
      #pragma unroll
      for (int e = 0; e < NELEM; e++){
        d_elptr[e] = b; curs[e] = b;
        b += (hist[e] + 31) & ~31;
      }
      d_elptr[NELEM] = b;
    }
    for (int i = tid; i < NBY_PAD; i += 256) d_nbyel[i] = -1;
    __syncthreads();
    #pragma unroll
    for (int q = 0; q < 32; q++){
      int p = atomicAdd(&curs[els[q]], 1);
      d_nbyel[p] = q*256 + tid;
    }
  } else {
    __shared__ float wr[64];
    int el = blockIdx.x - 1, f = threadIdx.x;
    if (f < 64) wr[f] = w_read[f];
    __syncthreads();
    const float* W = Wprod + (NELEM + el)*16384 + f*64;
    float acc = 0.f;
    #pragma unroll
    for (int c = 0; c < 64; c++) acc += wr[c]*W[c];
    d_dB1e[el*256 + f] = acc;
  }
}

// ======== staged forward gather over nbr list ========
template<int LAYER>
__device__ __forceinline__ void gather_core(
    int n, int lane, int dg, const float* __restrict__ Wemb,
    const float wr0[8], const float wr1[8],
    float a0[16], float a1[16])
{
  const unsigned FM = 0xffffffffu;
  for (int base = 0; base < dg; base += 32){
    int j = base + lane;
    int jj = (j < dg) ? j : 0;
    int2 es = d_nbr[n*CAP + jj];
    int e = es.x, s = es.y;
    int els = (LAYER == 0) ? d_elem[s] : 0;
    float4 R0 = *(const float4*)(d_Rb + e*8);
    float4 R1 = *(const float4*)(d_Rb + e*8 + 4);
    const float4* Yp = (const float4*)(d_Y + e*16);
    float4 Y0 = Yp[0], Y1 = Yp[1], Y2 = Yp[2], Y3 = Yp[3];
    int m = min(32, dg - base);
    for (int k = 0; k < m; k++){
      int sk = __shfl_sync(FM, s, k);
      float hv0, hv1;
      if (LAYER == 0){
        int elk = __shfl_sync(FM, els, k);
        hv0 = Wemb[elk*64 + lane]; hv1 = Wemb[elk*64 + 32 + lane];
      } else {
        hv0 = d_h1[sk*64 + lane]; hv1 = d_h1[sk*64 + 32 + lane];
      }
      float rb, w0, w1;
      rb = __shfl_sync(FM, R0.x, k); w0  = rb*wr0[0]; w1  = rb*wr1[0];
      rb = __shfl_sync(FM, R0.y, k); w0 += rb*wr0[1]; w1 += rb*wr1[1];
      rb = __shfl_sync(FM, R0.z, k); w0 += rb*wr0[2]; w1 += rb*wr1[2];
      rb = __shfl_sync(FM, R0.w, k); w0 += rb*wr0[3]; w1 += rb*wr1[3];
      rb = __shfl_sync(FM, R1.x, k); w0 += rb*wr0[4]; w1 += rb*wr1[4];
      rb = __shfl_sync(FM, R1.y, k); w0 += rb*wr0[5]; w1 += rb*wr1[5];
      rb = __shfl_sync(FM, R1.z, k); w0 += rb*wr0[6]; w1 += rb*wr1[6];
      rb = __shfl_sync(FM, R1.w, k); w0 += rb*wr0[7]; w1 += rb*wr1[7];
      float wh0 = w0*hv0, wh1 = w1*hv1;
      float yk;
      yk = __shfl_sync(FM, Y0.x, k); a0[0]  += wh0*yk; a1[0]  += wh1*yk;
      yk = __shfl_sync(FM, Y0.y, k); a0[1]  += wh0*yk; a1[1]  += wh1*yk;
      yk = __shfl_sync(FM, Y0.z, k); a0[2]  += wh0*yk; a1[2]  += wh1*yk;
      yk = __shfl_sync(FM, Y0.w, k); a0[3]  += wh0*yk; a1[3]  += wh1*yk;
      yk = __shfl_sync(FM, Y1.x, k); a0[4]  += wh0*yk; a1[4]  += wh1*yk;
      yk = __shfl_sync(FM, Y1.y, k); a0[5]  += wh0*yk; a1[5]  += wh1*yk;
      yk = __shfl_sync(FM, Y1.z, k); a0[6]  += wh0*yk; a1[6]  += wh1*yk;
      yk = __shfl_sync(FM, Y1.w, k); a0[7]  += wh0*yk; a1[7]  += wh1*yk;
      yk = __shfl_sync(FM, Y2.x, k); a0[8]  += wh0*yk; a1[8]  += wh1*yk;
      yk = __shfl_sync(FM, Y2.y, k); a0[9]  += wh0*yk; a1[9]  += wh1*yk;
      yk = __shfl_sync(FM, Y2.z, k); a0[10] += wh0*yk; a1[10] += wh1*yk;
      yk = __shfl_sync(FM, Y2.w, k); a0[11] += wh0*yk; a1[11] += wh1*yk;
      yk = __shfl_sync(FM, Y3.x, k); a0[12] += wh0*yk; a1[12] += wh1*yk;
      yk = __shfl_sync(FM, Y3.y, k); a0[13] += wh0*yk; a1[13] += wh1*yk;
      yk = __shfl_sync(FM, Y3.z, k); a0[14] += wh0*yk; a1[14] += wh1*yk;
      yk = __shfl_sync(FM, Y3.w, k); a0[15] += wh0*yk; a1[15] += wh1*yk;
    }
  }
}

// ---------------- gather layer 0: A (float2 pairs) + B ----------------
__global__ void k_gather0(const float* __restrict__ Wemb, const float* __restrict__ Wrad){
  int n = blockIdx.x*4 + (threadIdx.x >> 5);
  int lane = threadIdx.x & 31;
  float wr0[8], wr1[8];
  #pragma unroll
  for (int b = 0; b < 8; b++){ wr0[b] = Wrad[b*64+lane]; wr1[b] = Wrad[b*64+32+lane]; }
#if __CUDA_ARCH__ >= 900
  cudaGridDependencySynchronize();
#endif
  float a0[16], a1[16];
  #pragma unroll
  for (int i = 0; i < 16; i++){ a0[i] = 0.f; a1[i] = 0.f; }
  int dg = min(d_deg[n], CAP);
  gather_core<0>(n, lane, dg, Wemb, wr0, wr1, a0, a1);
  float2* A2 = (float2*)(d_A + n*1024);
  #pragma unroll
  for (int lm = 0; lm < 16; lm++) A2[lm*32 + lane] = make_float2(a0[lm], a1[lm]);
  float b0[4] = {0,0,0,0}, b1[4] = {0,0,0,0};
  #pragma unroll
  for (int lm = 0; lm < 16; lm++){
    int l = (lm == 0) ? 0 : (lm < 4) ? 1 : (lm < 9) ? 2 : 3;
    b0[l] += a0[lm]*a0[lm]; b1[l] += a1[lm]*a1[lm];
  }
  #pragma unroll
  for (int l = 0; l < 4; l++){
    d_Bf[n*256 + l*64 + lane]      = b0[l];
    d_Bf[n*256 + l*64 + 32 + lane] = b1[l];
  }
}

// ---------------- staged per-edge backward core; forces -> out ----------------
template<int LAYER>
__device__ __forceinline__ void edge_bwd_loop(
    int n, int lane, int dg, const float* __restrict__ Wemb,
    const float dA0[16], const float dA1[16],
    const float wr0[8], const float wr1[8],
    float* __restrict__ fout)
{
  const unsigned FM = 0xffffffffu;
  float accx = 0.f, accy = 0.f, accz = 0.f;
  const float c1 = 0.4886025119029199f;
  for (int base = 0; base < dg; base += 32){
    int j = base + lane;
    int jj = (j < dg) ? j : 0;
    int2 es = d_nbr[n*CAP + jj];
    int e = es.x, s = es.y;
    int els = (LAYER == 0) ? d_elem[s] : 0;
    float4 R0 = *(const float4*)(d_Rb + e*8);
    float4 R1 = *(const float4*)(d_Rb + e*8 + 4);
    float4 D0 = *(const float4*)(d_dRb + e*8);
    float4 D1 = *(const float4*)(d_dRb + e*8 + 4);
    const float4* Yp = (const float4*)(d_Y + e*16);
    float4 Y0 = Yp[0], Y1 = Yp[1], Y2 = Yp[2], Y3 = Yp[3];
    float vx = d_vec[3*e], vy = d_vec[3*e+1], vz = d_vec[3*e+2];
    float vi = d_r[e];
    int m = min(32, dg - base);
    for (int k = 0; k < m; k++){
      int sk = __shfl_sync(FM, s, k);
      float hv0, hv1;
      if (LAYER == 1){
        hv0 = d_h1[sk*64 + lane]; hv1 = d_h1[sk*64 + 32 + lane];
      } else {
        int elk = __shfl_sync(FM, els, k);
        hv0 = Wemb[elk*64 + lane]; hv1 = Wemb[elk*64 + 32 + lane];
      }
      float rb, db, w0, w1, s0, s1;
      rb = __shfl_sync(FM, R0.x, k); w0  = rb*wr0[0]; w1  = rb*wr1[0];
      rb = __shfl_sync(FM, R0.y, k); w0 += rb*wr0[1]; w1 += rb*wr1[1];
      rb = __shfl_sync(FM, R0.z, k); w0 += rb*wr0[2]; w1 += rb*wr1[2];
      rb = __shfl_sync(FM, R0.w, k); w0 += rb*wr0[3]; w1 += rb*wr1[3];
      rb = __shfl_sync(FM, R1.x, k); w0 += rb*wr0[4]; w1 += rb*wr1[4];
      rb = __shfl_sync(FM, R1.y, k); w0 += rb*wr0[5]; w1 += rb*wr1[5];
      rb = __shfl_sync(FM, R1.z, k); w0 += rb*wr0[6]; w1 += rb*wr1[6];
      rb = __shfl_sync(FM, R1.w, k); w0 += rb*wr0[7]; w1 += rb*wr1[7];
      db = __shfl_sync(FM, D0.x, k); s0  = db*wr0[0]; s1  = db*wr1[0];
      db = __shfl_sync(FM, D0.y, k); s0 += db*wr0[1]; s1 += db*wr1[1];
      db = __shfl_sync(FM, D0.z, k); s0 += db*wr0[2]; s1 += db*wr1[2];
      db = __shfl_sync(FM, D0.w, k); s0 += db*wr0[3]; s1 += db*wr1[3];
      db = __shfl_sync(FM, D1.x, k); s0 += db*wr0[4]; s1 += db*wr1[4];
      db = __shfl_sync(FM, D1.y, k); s0 += db*wr0[5]; s1 += db*wr1[5];
      db = __shfl_sync(FM, D1.z, k); s0 += db*wr0[6]; s1 += db*wr1[6];
      db = __shfl_sync(FM, D1.w, k); s0 += db*wr0[7]; s1 += db*wr1[7];
      float Yv[16];
      Yv[0]  = __shfl_sync(FM, Y0.x, k); Yv[1]  = __shfl_sync(FM, Y0.y, k);
      Yv[2]  = __shfl_sync(FM, Y0.z, k); Yv[3]  = __shfl_sync(FM, Y0.w, k);
      Yv[4]  = __shfl_sync(FM, Y1.x, k); Yv[5]  = __shfl_sync(FM, Y1.y, k);
      Yv[6]  = __shfl_sync(FM, Y1.z, k); Yv[7]  = __shfl_sync(FM, Y1.w, k);
      Yv[8]  = __shfl_sync(FM, Y2.x, k); Yv[9]  = __shfl_sync(FM, Y2.y, k);
      Yv[10] = __shfl_sync(FM, Y2.z, k); Yv[11] = __shfl_sync(FM, Y2.w, k);
      Yv[12] = __shfl_sync(FM, Y3.x, k); Yv[13] = __shfl_sync(FM, Y3.y, k);
      Yv[14] = __shfl_sync(FM, Y3.z, k); Yv[15] = __shfl_sync(FM, Y3.w, k);
      float x = __shfl_sync(FM, vx, k);
      float y = __shfl_sync(FM, vy, k);
      float z = __shfl_sync(FM, vz, k);
      float inv = __shfl_sync(FM, vi, k);
      float g0 = 0.f, g1 = 0.f;
      #pragma unroll
      for (int lm = 0; lm < 16; lm++){ g0 += dA0[lm]*Yv[lm]; g1 += dA1[lm]*Yv[lm]; }
      float wh0 = w0*hv0, wh1 = w1*hv1;
      float x2my2 = x*x - y*y;
      float z2 = z*z;
      float c4x = 1.0925484305920792f*x, c4y = 1.0925484305920792f*y, c4z = 1.0925484305920792f*z;
      float txy = 2.890611442640554f*x*y, txz = 2.890611442640554f*x*z, tyz = 2.890611442640554f*y*z;
      float q13 = 0.4570457994644658f*(5.f*z2 - 1.f);
      float e9  = 3.540261539559861f*x*y;
      float e15 = 1.7701307697799304f*x2my2;
      float pz6 = 1.8923493915151203f*z;
      float q11y = 4.570457994644658f*y*z, q11x = 4.570457994644658f*x*z;
      float p12 = 0.3731763325901154f*(15.f*z2 - 3.f);
      float p14 = 1.445305721320277f*x2my2;
      float px0 = c1*dA0[3] + c4y*dA0[4] + c4z*dA0[7] + c4x*dA0[8] + e9*dA0[9]
                + tyz*dA0[10] + q13*dA0[13] + txz*dA0[14] + e15*dA0[15];
      float py0 = c1*dA0[1] + c4x*dA0[4] + c4z*dA0[5] - c4y*dA0[8] + e15*dA0[9]
                + txz*dA0[10] + q13*dA0[11] - tyz*dA0[14] - e9*dA0[15];
      float pz0 = c1*dA0[2] + c4y*dA0[5] + pz6*dA0[6] + c4x*dA0[7] + txy*dA0[10]
                + q11y*dA0[11] + p12*dA0[12] + q11x*dA0[13] + p14*dA0[14];
      float px1 = c1*dA1[3] + c4y*dA1[4] + c4z*dA1[7] + c4x*dA1[8] + e9*dA1[9]
                + tyz*dA1[10] + q13*dA1[13] + txz*dA1[14] + e15*dA1[15];
      float py1 = c1*dA1[1] + c4x*dA1[4] + c4z*dA1[5] - c4y*dA1[8] + e15*dA1[9]
                + txz*dA1[10] + q13*dA1[11] - tyz*dA1[14] - e9*dA1[15];
      float pz1 = c1*dA1[2] + c4y*dA1[5] + pz6*dA1[6] + c4x*dA1[7] + txy*dA1[10]
                + q11y*dA1[11] + p12*dA1[12] + q11x*dA1[13] + p14*dA1[14];
      float pgx = wh0*px0 + wh1*px1;
      float pgy = wh0*py0 + wh1*py1;
      float pgz = wh0*pz0 + wh1*pz1;
      float prad = g0*hv0*s0 + g1*hv1*s1;
      BFLY(pgx); BFLY(pgy); BFLY(pgz); BFLY(prad);
      if (lane == 0){
        float gdotu = pgx*x + pgy*y + pgz*z;
        float dvx = inv*(pgx - gdotu*x) + prad*x;
        float dvy = inv*(pgy - gdotu*y) + prad*y;
        float dvz = inv*(pgz - gdotu*z) + prad*z;
        accx += dvx; accy += dvy; accz += dvz;
        atomicAdd(&fout[3*sk],   dvx);
        atomicAdd(&fout[3*sk+1], dvy);
        atomicAdd(&fout[3*sk+2], dvz);
      }
      if (LAYER == 1){
        atomicAdd(&d_dh1[sk*64 + lane],      g0*w0);
        atomicAdd(&d_dh1[sk*64 + 32 + lane], g1*w1);
      }
    }
  }
  if (lane == 0 && dg > 0){
    atomicAdd(&fout[3*n],   -accx);
    atomicAdd(&fout[3*n+1], -accy);
    atomicAdd(&fout[3*n+2], -accz);
  }
}

// ---------------- fused layer-1 gather (B) + layer-1 backward ----------------
__global__ void k_gfused1(const float* __restrict__ Wemb, const float* __restrict__ Wrad,
                          float* __restrict__ out){
  int n = blockIdx.x*4 + (threadIdx.x >> 5);
  int lane = threadIdx.x & 31;
  float wr0[8], wr1[8];
  #pragma unroll
  for (int b = 0; b < 8; b++){ wr0[b] = Wrad[b*64+lane]; wr1[b] = Wrad[b*64+32+lane]; }
#if __CUDA_ARCH__ >= 900
  cudaGridDependencySynchronize();
#endif
  float a0[16], a1[16];
  #pragma unroll
  for (int i = 0; i < 16; i++){ a0[i] = 0.f; a1[i] = 0.f; }
  int dg = min(d_deg[n], CAP);
  gather_core<1>(n, lane, dg, Wemb, wr0, wr1, a0, a1);
  float b0[4] = {0,0,0,0}, b1[4] = {0,0,0,0};
  #pragma unroll
  for (int lm = 0; lm < 16; lm++){
    int l = (lm == 0) ? 0 : (lm < 4) ? 1 : (lm < 9) ? 2 : 3;
    b0[l] += a0[lm]*a0[lm]; b1[l] += a1[lm]*a1[lm];
  }
  #pragma unroll
  for (int l = 0; l < 4; l++){
    d_Bf[n*256 + l*64 + lane]      = b0[l];
    d_Bf[n*256 + l*64 + 32 + lane] = b1[l];
  }
  if (dg == 0) return;
  const float* dB = d_dB1e + d_elem[n]*256;
  #pragma unroll
  for (int lm = 0; lm < 16; lm++){
    int l = (lm == 0) ? 0 : (lm < 4) ? 1 : (lm < 9) ? 2 : 3;
    a0[lm] = 2.f*a0[lm]*dB[l*64 + lane];
    a1[lm] = 2.f*a1[lm]*dB[l*64 + 32 + lane];
  }
  edge_bwd_loop<1>(n, lane, dg, Wemb, a0, a1, wr0, wr1, out + GG);
}

// --- warp-per-2-nodes GEMM: 16-node tiles, B in regs, 64KB weights, shfl bcast ----
// 256 threads = 8 warps x 2 nodes; grid NTILES16 (532)
#define GH_SMEM (16384*4 + GG*4 + 16*4 + 128)
template<int LAYER>
__global__ void __launch_bounds__(256, 3)
k_gemm_h(const float* __restrict__ Wprod, const float* __restrict__ w_read,
         const float* __restrict__ ae, const int* __restrict__ batch,
         float* __restrict__ out){
  extern __shared__ float sm[];
  float* Ws = sm;                        // [256 f][64 c]
  float* engs = sm + 16384;              // [16]
  int* nids = (int*)(engs + GG);         // [16]
  int base = blockIdx.x*16;
  if (base >= d_elptr[NELEM]) return;
  int el = 0;
  #pragma unroll
  for (int e = 1; e < NELEM; e++) if (d_elptr[e] <= base) el = e;
  int tid = threadIdx.x;                 // 256
  const float4* W4 = (const float4*)(Wprod + (LAYER*NELEM + el)*16384);
  float4* Ws4 = (float4*)Ws;
  #pragma unroll
  for (int i = 0; i < 16; i++) Ws4[tid + i*256] = W4[tid + i*256];
  if (tid < 16) nids[tid] = d_nbyel[base + tid];
  if (LAYER == 1 && tid < GG) engs[tid] = 0.f;
  __syncthreads();
#if __CUDA_ARCH__ >= 900
  cudaGridDependencySynchronize();      // weight-load prologue overlapped with producer
#endif
  const unsigned FM = 0xffffffffu;
  int w = tid >> 5, lane = tid & 31;
  int n0 = nids[2*w], n1 = nids[2*w + 1];
  float Br0[8], Br1[8];
  {
    const float* B0p = d_Bf + (n0 >= 0 ? n0 : 0)*256;
    const float* B1p = d_Bf + (n1 >= 0 ? n1 : 0)*256;
    #pragma unroll
    for (int q = 0; q < 8; q++){
      Br0[q] = (n0 >= 0) ? B0p[q*32 + lane] : 0.f;
      Br1[q] = (n1 >= 0) ? B1p[q*32 + lane] : 0.f;
    }
  }
  const ull* Wsu = (const ull*)Ws;       // [256 f][32 channel-pairs]
  ull acc0 = 0, acc1 = 0;
  #pragma unroll
  for (int q = 0; q < 8; q++){
    #pragma unroll
    for (int kk = 0; kk < 32; kk += 2){
      float b0a = __shfl_sync(FM, Br0[q], kk), b0b = __shfl_sync(FM, Br0[q], kk+1);
      float b1a = __shfl_sync(FM, Br1[q], kk), b1b = __shfl_sync(FM, Br1[q], kk+1);
      ull wva = Wsu[(q*32 + kk)*32 + lane];
      ull wvb = Wsu[(q*32 + kk + 1)*32 + lane];
      FFMA2(acc0, packf2(b0a, b0a), wva, acc0);
      FFMA2(acc1, packf2(b1a, b1a), wva, acc1);
      FFMA2(acc0, packf2(b0b, b0b), wvb, acc0);
      FFMA2(acc1, packf2(b1b, b1b), wvb, acc1);
    }
  }
  if (LAYER == 0){
    if (n0 >= 0) ((ull*)(d_h1 + n0*64))[lane] = acc0;
    if (n1 >= 0) ((ull*)(d_h1 + n1*64))[lane] = acc1;
  } else {
    float wlo = w_read[2*lane], whi = w_read[2*lane + 1];
    #pragma unroll
    for (int i = 0; i < 2; i++){
      ull a = (i == 0) ? acc0 : acc1;
      int nn = (i == 0) ? n0 : n1;
      float lo, hi; unpackf2(a, lo, hi);
      float p = lo*wlo + hi*whi;
      BFLY(p);
      if (lane == 0 && nn >= 0)
        atomicAdd(&engs[batch[nn]], p + ae[el]);
    }
    __syncthreads();
    if (tid < GG){
      float v = engs[tid];
      if (v != 0.f) atomicAdd(&out[tid], v);
    }
  }
}

// ---------------- fused: dB0 tile (smem) + layer-0 backward; cleans dh1+deg -------
#define BWD0_SMEM (64*264*4 + 32*66*4 + 32*256*4 + 128)
__global__ void k_bwd0(const float* __restrict__ Wprod, const float* __restrict__ Wemb,
                       const float* __restrict__ Wrad, float* __restrict__ out){
  extern __shared__ float sm[];
  float* Wt  = sm;                        // [c][f] 64 x 264
  float* dhs = sm + 64*264;               // [node][c] 32 x 66
  float* dBs = sm + 64*264 + 32*66;       // [node][f] 32 x 256
  int* nids  = (int*)(sm + 64*264 + 32*66 + 32*256);
  int base = blockIdx.x*32;
  if (base >= d_elptr[NELEM]) return;
  int el = 0;
  #pragma unroll
  for (int e = 1; e < NELEM; e++) if (d_elptr[e] <= base) el = e;
  int tid = threadIdx.x;   // 256
  const float* W = Wprod + el*16384;
  for (int i = tid; i < 16384; i += 256){
    int f = i >> 6, c = i & 63;
    Wt[c*264 + f] = W[i];
  }
  if (tid < 32) nids[tid] = d_nbyel[base + tid];
  __syncthreads();
#if __CUDA_ARCH__ >= 900
  cudaGridDependencySynchronize();      // weight-load prologue overlapped with gfused1
#endif
  for (int i = tid; i < 32*64; i += 256){
    int k = i >> 6, c = i & 63;
    int nn = nids[k];
    if (nn >= 0){
      dhs[k*66 + c] = d_dh1[nn*64 + c];
      d_dh1[nn*64 + c] = 0.f;             // self-clean for next replay
    } else {
      dhs[k*66 + c] = 0.f;
    }
  }
  __syncthreads();
  {
    int ng = tid >> 4, fg = tid & 15;
    float acc0[16], acc1[16];
    #pragma unroll
    for (int i = 0; i < 16; i++){ acc0[i] = 0.f; acc1[i] = 0.f; }
    #pragma unroll 2
    for (int c = 0; c < 64; c++){
      float dd0 = dhs[(2*ng)*66 + c];
      float dd1 = dhs[(2*ng+1)*66 + c];
      const float4* Wc = (const float4*)(Wt + c*264 + fg*16);
      #pragma unroll
      for (int q = 0; q < 4; q++){
        float4 w = Wc[q];
        acc0[4*q]   += dd0*w.x; acc0[4*q+1] += dd0*w.y; acc0[4*q+2] += dd0*w.z; acc0[4*q+3] += dd0*w.w;
        acc1[4*q]   += dd1*w.x; acc1[4*q+1] += dd1*w.y; acc1[4*q+2] += dd1*w.z; acc1[4*q+3] += dd1*w.w;
      }
    }
    float4* o0 = (float4*)(dBs + (2*ng)*256 + fg*16);
    float4* o1 = (float4*)(dBs + (2*ng+1)*256 + fg*16);
    #pragma unroll
    for (int q = 0; q < 4; q++){
      o0[q] = make_float4(acc0[4*q],acc0[4*q+1],acc0[4*q+2],acc0[4*q+3]);
      o1[q] = make_float4(acc1[4*q],acc1[4*q+1],acc1[4*q+2],acc1[4*q+3]);
    }
  }
  __syncthreads();
  int w = tid >> 5, lane = tid & 31;
  float wr0[8], wr1[8];
  #pragma unroll
  for (int b = 0; b < 8; b++){ wr0[b] = Wrad[b*64+lane]; wr1[b] = Wrad[b*64+32+lane]; }
  for (int q = 0; q < 4; q++){
    int nloc = w*4 + q;
    int nn = nids[nloc];
    if (nn < 0) continue;
    int dg = min(d_deg[nn], CAP);
    if (lane == 0) d_deg[nn] = 0;         // self-clean for next replay
    if (dg == 0) continue;
    const float* dB = dBs + nloc*256;
    const float2* A2 = (const float2*)(d_A + nn*1024);
    float dA0[16], dA1[16];
    #pragma unroll
    for (int lm = 0; lm < 16; lm++){
      int l = (lm == 0) ? 0 : (lm < 4) ? 1 : (lm < 9) ? 2 : 3;
      float2 av = A2[lm*32 + lane];
      dA0[lm] = 2.f*av.x*dB[l*64 + lane];
      dA1[lm] = 2.f*av.y*dB[l*64 + 32 + lane];
    }
    edge_bwd_loop<0>(nn, lane, dg, Wemb, dA0, dA1, wr0, wr1, out + GG);
  }
}

// ---------------- launch ----------------
extern "C" void kernel_launch(void* const* d_in, const int* in_sizes, int n_in,
                              void* d_out, int out_size){
  const float* pos    = (const float*)d_in[0];
  const float* attrs  = (const float*)d_in[1];
  const float* shifts = (const float*)d_in[2];
  const float* Wemb   = (const float*)d_in[3];
  const float* aew    = (const float*)d_in[4];
  const float* Wrad   = (const float*)d_in[5];
  const float* Wprod  = (const float*)d_in[6];
  const float* wread  = (const float*)d_in[7];
  const int*   ei     = (const int*)d_in[8];
  const int*   batch  = (const int*)d_in[9];
  float* out = (float*)d_out;

  static cudaStream_t s2 = nullptr;
  static cudaEvent_t ev0 = nullptr, evM = nullptr, ev1 = nullptr, ev2 = nullptr;
  if (!s2){
    cudaFuncSetAttribute(k_gemm_h<0>, cudaFuncAttributeMaxDynamicSharedMemorySize, GH_SMEM);
    cudaFuncSetAttribute(k_gemm_h<1>, cudaFuncAttributeMaxDynamicSharedMemorySize, GH_SMEM);
    cudaFuncSetAttribute(k_bwd0,      cudaFuncAttributeMaxDynamicSharedMemorySize, BWD0_SMEM);
    cudaStreamCreateWithFlags(&s2, cudaStreamNonBlocking);
    cudaEventCreateWithFlags(&ev0, cudaEventDisableTiming);
    cudaEventCreateWithFlags(&evM, cudaEventDisableTiming);
    cudaEventCreateWithFlags(&ev1, cudaEventDisableTiming);
    cudaEventCreateWithFlags(&ev2, cudaEventDisableTiming);
  }

  // fork misc (element grouping + dB1e) — depends only on inputs
  cudaEventRecord(ev0, 0);
  cudaStreamWaitEvent(s2, ev0, 0);
  k_misc<<<1 + NELEM, 256, 0, s2>>>(attrs, Wprod, wread);
  cudaEventRecord(evM, s2);

  k_geom<<<256 + (OUTSZ + 255)/256, 256>>>(pos, shifts, ei, attrs, out);

  cudaLaunchAttribute pdl[1];
  pdl[0].id = cudaLaunchAttributeProgrammaticStreamSerialization;
  pdl[0].val.programmaticStreamSerializationAllowed = 1;

  {
    cudaLaunchConfig_t cfg = {};
    cfg.gridDim = dim3(NN/4); cfg.blockDim = dim3(128);
    cfg.dynamicSmemBytes = 0; cfg.stream = 0;
    cfg.attrs = pdl; cfg.numAttrs = 1;
    cudaLaunchKernelEx(&cfg, k_gather0, Wemb, Wrad);
  }
  cudaStreamWaitEvent(0, evM, 0);
  {
    cudaLaunchConfig_t cfg = {};
    cfg.gridDim = dim3(NTILES16); cfg.blockDim = dim3(256);
    cfg.dynamicSmemBytes = GH_SMEM; cfg.stream = 0;
    cfg.attrs = pdl; cfg.numAttrs = 1;
    cudaLaunchKernelEx(&cfg, k_gemm_h<0>, Wprod, wread, aew, batch, out);
  }
  {
    cudaLaunchConfig_t cfg = {};
    cfg.gridDim = dim3(NN/4); cfg.blockDim = dim3(128);
    cfg.dynamicSmemBytes = 0; cfg.stream = 0;
    cfg.attrs = pdl; cfg.numAttrs = 1;
    cudaLaunchKernelEx(&cfg, k_gfused1, Wemb, Wrad + 512, out);
  }

  // fork: energy GEMM (s2) concurrent with layer-0 backward (stream 0)
  cudaEventRecord(ev1, 0);
  cudaStreamWaitEvent(s2, ev1, 0);
  k_gemm_h<1><<<NTILES16, 256, GH_SMEM, s2>>>(Wprod, wread, aew, batch, out);
  cudaEventRecord(ev2, s2);

  {
    cudaLaunchConfig_t cfg = {};
    cfg.gridDim = dim3(NTILES); cfg.blockDim = dim3(256);
    cfg.dynamicSmemBytes = BWD0_SMEM; cfg.stream = 0;
    cfg.attrs = pdl; cfg.numAttrs = 1;
    cudaLaunchKernelEx(&cfg, k_bwd0, Wprod, Wemb, Wrad, out);
  }
  cudaStreamWaitEvent(0, ev2, 0);
}

// round 17
// speedup vs baseline: 1.6115x; 1.1241x over previous
#include <cuda_runtime.h>

#define NN 8192
#define EE 65536
#define GG 16
#define NELEM 10
#define CAP 32
#define NBY_PAD (NN + 32*NELEM)
#define NTILES (NBY_PAD/32)
#define OUTSZ (GG + NN*3)

typedef unsigned long long ull;

// ---------------- persistent device scratch (zero-init at load; self-cleaned) ----
__device__ float d_vec[EE*3];
__device__ float d_r[EE];
__device__ float d_Y[EE*16];
__device__ float d_Rb[EE*8];
__device__ float d_dRb[EE*8];
__device__ float d_A[NN*1024];
__device__ float d_Bf[NN*256];
__device__ float d_h1[NN*64];
__device__ float d_dh1[NN*64];
__device__ float d_dB1e[NELEM*256];
__device__ int   d_elem[NN];
__device__ int   d_deg[NN];            // zeroed by k_bwd0 each replay
__device__ int2  d_nbr[NN*CAP];        // (edge, sender)
__device__ int   d_elptr[NELEM+1];
__device__ int   d_nbyel[NBY_PAD];

#define BFLY(p) { _Pragma("unroll") for (int off = 16; off > 0; off >>= 1) p += __shfl_xor_sync(0xffffffffu, p, off); }
#define FFMA2(d,a,b,c) asm("fma.rn.f32x2 %0,%1,%2,%3;" : "=l"(d) : "l"(a), "l"(b), "l"(c))
__device__ __forceinline__ ull packf2(float lo, float hi){
  ull r; asm("mov.b64 %0,{%1,%2};" : "=l"(r) : "f"(lo), "f"(hi)); return r;
}
__device__ __forceinline__ void unpackf2(ull v, float& lo, float& hi){
  asm("mov.b64 {%0,%1},%2;" : "=f"(lo), "=f"(hi) : "l"(v));
}

// ---------------- geometry + nbr-list append ; elem / out-zero (rest) --------------
__global__ void k_geom(const float* __restrict__ pos, const float* __restrict__ shifts,
                       const int* __restrict__ ei, const float* __restrict__ attrs,
                       float* __restrict__ out){
  if (blockIdx.x >= 256){
    int i = (blockIdx.x - 256)*256 + threadIdx.x;
    if (i < OUTSZ) out[i] = 0.f;
    if (i < NN){
      int el = 0;
      const float* a = attrs + i*NELEM;
      #pragma unroll
      for (int e = 1; e < NELEM; e++) if (a[e] > 0.5f) el = e;
      d_elem[i] = el;
    }
    return;
  }
  int e = blockIdx.x*256 + threadIdx.x;
  int s = ei[e], n = ei[EE+e];
  float vx = pos[3*n]   - pos[3*s]   + shifts[3*e];
  float vy = pos[3*n+1] - pos[3*s+1] + shifts[3*e+1];
  float vz = pos[3*n+2] - pos[3*s+2] + shifts[3*e+2];
  float r = sqrtf(vx*vx + vy*vy + vz*vz + 1e-9f);
  float u = r*0.2f;
  if (u >= 1.f) return;
  int slot = atomicAdd(&d_deg[n], 1);
  if (slot < CAP) d_nbr[n*CAP + slot] = make_int2(e, s);
  float inv = 1.f/r;
  float x = vx*inv, y = vy*inv, z = vz*inv;
  d_vec[3*e] = x; d_vec[3*e+1] = y; d_vec[3*e+2] = z;
  d_r[e] = inv;
  float x2 = x*x, y2 = y*y, z2 = z*z;
  float* Y = d_Y + e*16;
  Y[0]  = 0.28209479177387814f;
  Y[1]  = 0.4886025119029199f*y;
  Y[2]  = 0.4886025119029199f*z;
  Y[3]  = 0.4886025119029199f*x;
  Y[4]  = 1.0925484305920792f*x*y;
  Y[5]  = 1.0925484305920792f*y*z;
  Y[6]  = 0.31539156525252005f*(3.f*z2 - 1.f);
  Y[7]  = 1.0925484305920792f*x*z;
  Y[8]  = 0.5462742152960396f*(x2 - y2);
  Y[9]  = 0.5900435899266435f*y*(3.f*x2 - y2);
  Y[10] = 2.890611442640554f*x*y*z;
  Y[11] = 0.4570457994644658f*y*(5.f*z2 - 1.f);
  Y[12] = 0.3731763325901154f*z*(5.f*z2 - 3.f);
  Y[13] = 0.4570457994644658f*x*(5.f*z2 - 1.f);
  Y[14] = 1.445305721320277f*z*(x2 - y2);
  Y[15] = 0.5900435899266435f*x*(x2 - 3.f*y2);
  float u2 = u*u; float u4 = u2*u2;
  float omu = 1.f - u;
  float cut  = 1.f + u4*u*(-21.f + u*(35.f - 15.f*u));
  float cutp = -105.f*u4*omu*omu;
  const float pref = 0.6324555320336759f;
  const float PI_F = 3.14159265358979323846f;
  float* R = d_Rb + e*8;
  float* D = d_dRb + e*8;
  #pragma unroll
  for (int b = 1; b <= 8; b++){
    float sp, cp;
    sincospif((float)b*u, &sp, &cp);
    R[b-1] = pref*sp*inv*cut;
    D[b-1] = pref*(((float)b*PI_F*0.2f)*cp*inv - sp*inv*inv)*cut
           + pref*sp*inv*cutp*0.2f;
  }
}

// ---------------- misc: element grouping (block 0) + dB1e (blocks 1..NELEM) ------
__global__ void k_misc(const float* __restrict__ attrs, const float* __restrict__ Wprod,
                       const float* __restrict__ w_read){
  if (blockIdx.x == 0){
    __shared__ int hist[NELEM], curs[NELEM];
    int tid = threadIdx.x;
    if (tid < NELEM) hist[tid] = 0;
    __syncthreads();
    int els[32];
    #pragma unroll
    for (int q = 0; q < 32; q++){
      int node = q*256 + tid;
      const float* a = attrs + node*NELEM;
      int el = 0;
      #pragma unroll
      for (int e = 1; e < NELEM; e++) if (a[e] > 0.5f) el = e;
      els[q] = el;
      atomicAdd(&hist[el], 1);
    }
    __syncthreads();
    if (tid == 0){
      int b = 0;
      #pragma unroll
      for (int e = 0; e < NELEM; e++){
        d_elptr[e] = b; curs[e] = b;
        b += (hist[e] + 31) & ~31;
      }
      d_elptr[NELEM] = b;
    }
    for (int i = tid; i < NBY_PAD; i += 256) d_nbyel[i] = -1;
    __syncthreads();
    #pragma unroll
    for (int q = 0; q < 32; q++){
      int p = atomicAdd(&curs[els[q]], 1);
      d_nbyel[p] = q*256 + tid;
    }
  } else {
    __shared__ float wr[64];
    int el = blockIdx.x - 1, f = threadIdx.x;
    if (f < 64) wr[f] = w_read[f];
    __syncthreads();
    const float* W = Wprod + (NELEM + el)*16384 + f*64;
    float acc = 0.f;
    #pragma unroll
    for (int c = 0; c < 64; c++) acc += wr[c]*W[c];
    d_dB1e[el*256 + f] = acc;
  }
}

// ======== staged forward gather over nbr list ========
template<int LAYER>
__device__ __forceinline__ void gather_core(
    int n, int lane, int dg, const float* __restrict__ Wemb,
    const float wr0[8], const float wr1[8],
    float a0[16], float a1[16])
{
  const unsigned FM = 0xffffffffu;
  for (int base = 0; base < dg; base += 32){
    int j = base + lane;
    int jj = (j < dg) ? j : 0;
    int2 es = d_nbr[n*CAP + jj];
    int e = es.x, s = es.y;
    int els = (LAYER == 0) ? d_elem[s] : 0;
    float4 R0 = *(const float4*)(d_Rb + e*8);
    float4 R1 = *(const float4*)(d_Rb + e*8 + 4);
    const float4* Yp = (const float4*)(d_Y + e*16);
    float4 Y0 = Yp[0], Y1 = Yp[1], Y2 = Yp[2], Y3 = Yp[3];
    int m = min(32, dg - base);
    for (int k = 0; k < m; k++){
      int sk = __shfl_sync(FM, s, k);
      float hv0, hv1;
      if (LAYER == 0){
        int elk = __shfl_sync(FM, els, k);
        hv0 = Wemb[elk*64 + lane]; hv1 = Wemb[elk*64 + 32 + lane];
      } else {
        hv0 = d_h1[sk*64 + lane]; hv1 = d_h1[sk*64 + 32 + lane];
      }
      float rb, w0, w1;
      rb = __shfl_sync(FM, R0.x, k); w0  = rb*wr0[0]; w1  = rb*wr1[0];
      rb = __shfl_sync(FM, R0.y, k); w0 += rb*wr0[1]; w1 += rb*wr1[1];
      rb = __shfl_sync(FM, R0.z, k); w0 += rb*wr0[2]; w1 += rb*wr1[2];
      rb = __shfl_sync(FM, R0.w, k); w0 += rb*wr0[3]; w1 += rb*wr1[3];
      rb = __shfl_sync(FM, R1.x, k); w0 += rb*wr0[4]; w1 += rb*wr1[4];
      rb = __shfl_sync(FM, R1.y, k); w0 += rb*wr0[5]; w1 += rb*wr1[5];
      rb = __shfl_sync(FM, R1.z, k); w0 += rb*wr0[6]; w1 += rb*wr1[6];
      rb = __shfl_sync(FM, R1.w, k); w0 += rb*wr0[7]; w1 += rb*wr1[7];
      float wh0 = w0*hv0, wh1 = w1*hv1;
      float yk;
      yk = __shfl_sync(FM, Y0.x, k); a0[0]  += wh0*yk; a1[0]  += wh1*yk;
      yk = __shfl_sync(FM, Y0.y, k); a0[1]  += wh0*yk; a1[1]  += wh1*yk;
      yk = __shfl_sync(FM, Y0.z, k); a0[2]  += wh0*yk; a1[2]  += wh1*yk;
      yk = __shfl_sync(FM, Y0.w, k); a0[3]  += wh0*yk; a1[3]  += wh1*yk;
      yk = __shfl_sync(FM, Y1.x, k); a0[4]  += wh0*yk; a1[4]  += wh1*yk;
      yk = __shfl_sync(FM, Y1.y, k); a0[5]  += wh0*yk; a1[5]  += wh1*yk;
      yk = __shfl_sync(FM, Y1.z, k); a0[6]  += wh0*yk; a1[6]  += wh1*yk;
      yk = __shfl_sync(FM, Y1.w, k); a0[7]  += wh0*yk; a1[7]  += wh1*yk;
      yk = __shfl_sync(FM, Y2.x, k); a0[8]  += wh0*yk; a1[8]  += wh1*yk;
      yk = __shfl_sync(FM, Y2.y, k); a0[9]  += wh0*yk; a1[9]  += wh1*yk;
      yk = __shfl_sync(FM, Y2.z, k); a0[10] += wh0*yk; a1[10] += wh1*yk;
      yk = __shfl_sync(FM, Y2.w, k); a0[11] += wh0*yk; a1[11] += wh1*yk;
      yk = __shfl_sync(FM, Y3.x, k); a0[12] += wh0*yk; a1[12] += wh1*yk;
      yk = __shfl_sync(FM, Y3.y, k); a0[13] += wh0*yk; a1[13] += wh1*yk;
      yk = __shfl_sync(FM, Y3.z, k); a0[14] += wh0*yk; a1[14] += wh1*yk;
      yk = __shfl_sync(FM, Y3.w, k); a0[15] += wh0*yk; a1[15] += wh1*yk;
    }
  }
}

// ---------------- gather layer 0: A (float2 pairs) + B ----------------
__global__ void k_gather0(const float* __restrict__ Wemb, const float* __restrict__ Wrad){
  int n = blockIdx.x*4 + (threadIdx.x >> 5);
  int lane = threadIdx.x & 31;
  float wr0[8], wr1[8];
  #pragma unroll
  for (int b = 0; b < 8; b++){ wr0[b] = Wrad[b*64+lane]; wr1[b] = Wrad[b*64+32+lane]; }
#if __CUDA_ARCH__ >= 900
  cudaGridDependencySynchronize();
#endif
  float a0[16], a1[16];
  #pragma unroll
  for (int i = 0; i < 16; i++){ a0[i] = 0.f; a1[i] = 0.f; }
  int dg = min(d_deg[n], CAP);
  gather_core<0>(n, lane, dg, Wemb, wr0, wr1, a0, a1);
  float2* A2 = (float2*)(d_A + n*1024);
  #pragma unroll
  for (int lm = 0; lm < 16; lm++) A2[lm*32 + lane] = make_float2(a0[lm], a1[lm]);
  float b0[4] = {0,0,0,0}, b1[4] = {0,0,0,0};
  #pragma unroll
  for (int lm = 0; lm < 16; lm++){
    int l = (lm == 0) ? 0 : (lm < 4) ? 1 : (lm < 9) ? 2 : 3;
    b0[l] += a0[lm]*a0[lm]; b1[l] += a1[lm]*a1[lm];
  }
  #pragma unroll
  for (int l = 0; l < 4; l++){
    d_Bf[n*256 + l*64 + lane]      = b0[l];
    d_Bf[n*256 + l*64 + 32 + lane] = b1[l];
  }
}

// ---------------- staged per-edge backward core; forces -> out ----------------
template<int LAYER>
__device__ __forceinline__ void edge_bwd_loop(
    int n, int lane, int dg, const float* __restrict__ Wemb,
    const float dA0[16], const float dA1[16],
    const float wr0[8], const float wr1[8],
    float* __restrict__ fout)
{
  const unsigned FM = 0xffffffffu;
  float accx = 0.f, accy = 0.f, accz = 0.f;
  const float c1 = 0.4886025119029199f;
  for (int base = 0; base < dg; base += 32){
    int j = base + lane;
    int jj = (j < dg) ? j : 0;
    int2 es = d_nbr[n*CAP + jj];
    int e = es.x, s = es.y;
    int els = (LAYER == 0) ? d_elem[s] : 0;
    float4 R0 = *(const float4*)(d_Rb + e*8);
    float4 R1 = *(const float4*)(d_Rb + e*8 + 4);
    float4 D0 = *(const float4*)(d_dRb + e*8);
    float4 D1 = *(const float4*)(d_dRb + e*8 + 4);
    const float4* Yp = (const float4*)(d_Y + e*16);
    float4 Y0 = Yp[0], Y1 = Yp[1], Y2 = Yp[2], Y3 = Yp[3];
    float vx = d_vec[3*e], vy = d_vec[3*e+1], vz = d_vec[3*e+2];
    float vi = d_r[e];
    int m = min(32, dg - base);
    for (int k = 0; k < m; k++){
      int sk = __shfl_sync(FM, s, k);
      float hv0, hv1;
      if (LAYER == 1){
        hv0 = d_h1[sk*64 + lane]; hv1 = d_h1[sk*64 + 32 + lane];
      } else {
        int elk = __shfl_sync(FM, els, k);
        hv0 = Wemb[elk*64 + lane]; hv1 = Wemb[elk*64 + 32 + lane];
      }
      float rb, db, w0, w1, s0, s1;
      rb = __shfl_sync(FM, R0.x, k); w0  = rb*wr0[0]; w1  = rb*wr1[0];
      rb = __shfl_sync(FM, R0.y, k); w0 += rb*wr0[1]; w1 += rb*wr1[1];
      rb = __shfl_sync(FM, R0.z, k); w0 += rb*wr0[2]; w1 += rb*wr1[2];
      rb = __shfl_sync(FM, R0.w, k); w0 += rb*wr0[3]; w1 += rb*wr1[3];
      rb = __shfl_sync(FM, R1.x, k); w0 += rb*wr0[4]; w1 += rb*wr1[4];
      rb = __shfl_sync(FM, R1.y, k); w0 += rb*wr0[5]; w1 += rb*wr1[5];
      rb = __shfl_sync(FM, R1.z, k); w0 += rb*wr0[6]; w1 += rb*wr1[6];
      rb = __shfl_sync(FM, R1.w, k); w0 += rb*wr0[7]; w1 += rb*wr1[7];
      db = __shfl_sync(FM, D0.x, k); s0  = db*wr0[0]; s1  = db*wr1[0];
      db = __shfl_sync(FM, D0.y, k); s0 += db*wr0[1]; s1 += db*wr1[1];
      db = __shfl_sync(FM, D0.z, k); s0 += db*wr0[2]; s1 += db*wr1[2];
      db = __shfl_sync(FM, D0.w, k); s0 += db*wr0[3]; s1 += db*wr1[3];
      db = __shfl_sync(FM, D1.x, k); s0 += db*wr0[4]; s1 += db*wr1[4];
      db = __shfl_sync(FM, D1.y, k); s0 += db*wr0[5]; s1 += db*wr1[5];
      db = __shfl_sync(FM, D1.z, k); s0 += db*wr0[6]; s1 += db*wr1[6];
      db = __shfl_sync(FM, D1.w, k); s0 += db*wr0[7]; s1 += db*wr1[7];
      float Yv[16];
      Yv[0]  = __shfl_sync(FM, Y0.x, k); Yv[1]  = __shfl_sync(FM, Y0.y, k);
      Yv[2]  = __shfl_sync(FM, Y0.z, k); Yv[3]  = __shfl_sync(FM, Y0.w, k);
      Yv[4]  = __shfl_sync(FM, Y1.x, k); Yv[5]  = __shfl_sync(FM, Y1.y, k);
      Yv[6]  = __shfl_sync(FM, Y1.z, k); Yv[7]  = __shfl_sync(FM, Y1.w, k);
      Yv[8]  = __shfl_sync(FM, Y2.x, k); Yv[9]  = __shfl_sync(FM, Y2.y, k);
      Yv[10] = __shfl_sync(FM, Y2.z, k); Yv[11] = __shfl_sync(FM, Y2.w, k);
      Yv[12] = __shfl_sync(FM, Y3.x, k); Yv[13] = __shfl_sync(FM, Y3.y, k);
      Yv[14] = __shfl_sync(FM, Y3.z, k); Yv[15] = __shfl_sync(FM, Y3.w, k);
      float x = __shfl_sync(FM, vx, k);
      float y = __shfl_sync(FM, vy, k);
      float z = __shfl_sync(FM, vz, k);
      float inv = __shfl_sync(FM, vi, k);
      float g0 = 0.f, g1 = 0.f;
      #pragma unroll
      for (int lm = 0; lm < 16; lm++){ g0 += dA0[lm]*Yv[lm]; g1 += dA1[lm]*Yv[lm]; }
      float wh0 = w0*hv0, wh1 = w1*hv1;
      float x2my2 = x*x - y*y;
      float z2 = z*z;
      float c4x = 1.0925484305920792f*x, c4y = 1.0925484305920792f*y, c4z = 1.0925484305920792f*z;
      float txy = 2.890611442640554f*x*y, txz = 2.890611442640554f*x*z, tyz = 2.890611442640554f*y*z;
      float q13 = 0.4570457994644658f*(5.f*z2 - 1.f);
      float e9  = 3.540261539559861f*x*y;
      float e15 = 1.7701307697799304f*x2my2;
      float pz6 = 1.8923493915151203f*z;
      float q11y = 4.570457994644658f*y*z, q11x = 4.570457994644658f*x*z;
      float p12 = 0.3731763325901154f*(15.f*z2 - 3.f);
      float p14 = 1.445305721320277f*x2my2;
      float px0 = c1*dA0[3] + c4y*dA0[4] + c4z*dA0[7] + c4x*dA0[8] + e9*dA0[9]
                + tyz*dA0[10] + q13*dA0[13] + txz*dA0[14] + e15*dA0[15];
      float py0 = c1*dA0[1] + c4x*dA0[4] + c4z*dA0[5] - c4y*dA0[8] + e15*dA0[9]
                + txz*dA0[10] + q13*dA0[11] - tyz*dA0[14] - e9*dA0[15];
      float pz0 = c1*dA0[2] + c4y*dA0[5] + pz6*dA0[6] + c4x*dA0[7] + txy*dA0[10]
                + q11y*dA0[11] + p12*dA0[12] + q11x*dA0[13] + p14*dA0[14];
      float px1 = c1*dA1[3] + c4y*dA1[4] + c4z*dA1[7] + c4x*dA1[8] + e9*dA1[9]
                + tyz*dA1[10] + q13*dA1[13] + txz*dA1[14] + e15*dA1[15];
      float py1 = c1*dA1[1] + c4x*dA1[4] + c4z*dA1[5] - c4y*dA1[8] + e15*dA1[9]
                + txz*dA1[10] + q13*dA1[11] - tyz*dA1[14] - e9*dA1[15];
      float pz1 = c1*dA1[2] + c4y*dA1[5] + pz6*dA1[6] + c4x*dA1[7] + txy*dA1[10]
                + q11y*dA1[11] + p12*dA1[12] + q11x*dA1[13] + p14*dA1[14];
      float pgx = wh0*px0 + wh1*px1;
      float pgy = wh0*py0 + wh1*py1;
      float pgz = wh0*pz0 + wh1*pz1;
      float prad = g0*hv0*s0 + g1*hv1*s1;
      BFLY(pgx); BFLY(pgy); BFLY(pgz); BFLY(prad);
      if (lane == 0){
        float gdotu = pgx*x + pgy*y + pgz*z;
        float dvx = inv*(pgx - gdotu*x) + prad*x;
        float dvy = inv*(pgy - gdotu*y) + prad*y;
        float dvz = inv*(pgz - gdotu*z) + prad*z;
        accx += dvx; accy += dvy; accz += dvz;
        atomicAdd(&fout[3*sk],   dvx);
        atomicAdd(&fout[3*sk+1], dvy);
        atomicAdd(&fout[3*sk+2], dvz);
      }
      if (LAYER == 1){
        atomicAdd(&d_dh1[sk*64 + lane],      g0*w0);
        atomicAdd(&d_dh1[sk*64 + 32 + lane], g1*w1);
      }
    }
  }
  if (lane == 0 && dg > 0){
    atomicAdd(&fout[3*n],   -accx);
    atomicAdd(&fout[3*n+1], -accy);
    atomicAdd(&fout[3*n+2], -accz);
  }
}

// ------ fused layer-1 gather (B) + ENERGY (B1·dB1e + ae) + layer-1 backward -------
__global__ void k_gfused1(const float* __restrict__ Wemb, const float* __restrict__ Wrad,
                          const float* __restrict__ ae, const int* __restrict__ batch,
                          float* __restrict__ out){
  int n = blockIdx.x*4 + (threadIdx.x >> 5);
  int lane = threadIdx.x & 31;
  float wr0[8], wr1[8];
  #pragma unroll
  for (int b = 0; b < 8; b++){ wr0[b] = Wrad[b*64+lane]; wr1[b] = Wrad[b*64+32+lane]; }
#if __CUDA_ARCH__ >= 900
  cudaGridDependencySynchronize();
#endif
  float a0[16], a1[16];
  #pragma unroll
  for (int i = 0; i < 16; i++){ a0[i] = 0.f; a1[i] = 0.f; }
  int dg = min(d_deg[n], CAP);
  gather_core<1>(n, lane, dg, Wemb, wr0, wr1, a0, a1);
  float b0[4] = {0,0,0,0}, b1[4] = {0,0,0,0};
  #pragma unroll
  for (int lm = 0; lm < 16; lm++){
    int l = (lm == 0) ? 0 : (lm < 4) ? 1 : (lm < 9) ? 2 : 3;
    b0[l] += a0[lm]*a0[lm]; b1[l] += a1[lm]*a1[lm];
  }
  #pragma unroll
  for (int l = 0; l < 4; l++){
    d_Bf[n*256 + l*64 + lane]      = b0[l];
    d_Bf[n*256 + l*64 + 32 + lane] = b1[l];
  }
  // energy: node_e = B1 . dB1e[elem] + ae[elem]   (h2 GEMM eliminated algebraically)
  int el = d_elem[n];
  const float* dB = d_dB1e + el*256;
  {
    float pe = 0.f;
    #pragma unroll
    for (int l = 0; l < 4; l++)
      pe += b0[l]*dB[l*64 + lane] + b1[l]*dB[l*64 + 32 + lane];
    BFLY(pe);
    if (lane == 0) atomicAdd(&out[batch[n]], pe + ae[el]);
  }
  if (dg == 0) return;
  #pragma unroll
  for (int lm = 0; lm < 16; lm++){
    int l = (lm == 0) ? 0 : (lm < 4) ? 1 : (lm < 9) ? 2 : 3;
    a0[lm] = 2.f*a0[lm]*dB[l*64 + lane];
    a1[lm] = 2.f*a1[lm]*dB[l*64 + 32 + lane];
  }
  edge_bwd_loop<1>(n, lane, dg, Wemb, a0, a1, wr0, wr1, out + GG);
}

// ------ warp-per-4-nodes GEMM (layer 0 only): B in regs, 64KB weights, shfl bcast --
#define GH_SMEM (16384*4 + 32*4 + 128)
__global__ void __launch_bounds__(256, 3)
k_gemm_h0(const float* __restrict__ Wprod){
  extern __shared__ float sm[];
  float* Ws = sm;                        // [256 f][64 c]
  int* nids = (int*)(sm + 16384);        // [32]
  int base = blockIdx.x*32;
  if (base >= d_elptr[NELEM]) return;
  int el = 0;
  #pragma unroll
  for (int e = 1; e < NELEM; e++) if (d_elptr[e] <= base) el = e;
  int tid = threadIdx.x;                 // 256
  const float4* W4 = (const float4*)(Wprod + el*16384);
  float4* Ws4 = (float4*)Ws;
  #pragma unroll
  for (int i = 0; i < 16; i++) Ws4[tid + i*256] = W4[tid + i*256];
  if (tid < 32) nids[tid] = d_nbyel[base + tid];
  __syncthreads();
#if __CUDA_ARCH__ >= 900
  cudaGridDependencySynchronize();      // weight-load prologue overlapped with producer
#endif
  const unsigned FM = 0xffffffffu;
  int w = tid >> 5, lane = tid & 31;
  int nn[4];
  float Br0[8], Br1[8], Br2[8], Br3[8];
  #pragma unroll
  for (int i = 0; i < 4; i++) nn[i] = nids[4*w + i];
  {
    const float* B0p = d_Bf + (nn[0] >= 0 ? nn[0] : 0)*256;
    const float* B1p = d_Bf + (nn[1] >= 0 ? nn[1] : 0)*256;
    const float* B2p = d_Bf + (nn[2] >= 0 ? nn[2] : 0)*256;
    const float* B3p = d_Bf + (nn[3] >= 0 ? nn[3] : 0)*256;
    #pragma unroll
    for (int q = 0; q < 8; q++){
      Br0[q] = (nn[0] >= 0) ? B0p[q*32 + lane] : 0.f;
      Br1[q] = (nn[1] >= 0) ? B1p[q*32 + lane] : 0.f;
      Br2[q] = (nn[2] >= 0) ? B2p[q*32 + lane] : 0.f;
      Br3[q] = (nn[3] >= 0) ? B3p[q*32 + lane] : 0.f;
    }
  }
  const ull* Wsu = (const ull*)Ws;       // [256 f][32 channel-pairs]
  ull acc0 = 0, acc1 = 0, acc2 = 0, acc3 = 0;
  #pragma unroll
  for (int q = 0; q < 8; q++){
    #pragma unroll
    for (int kk = 0; kk < 32; kk += 2){
      float b0a = __shfl_sync(FM, Br0[q], kk), b0b = __shfl_sync(FM, Br0[q], kk+1);
      float b1a = __shfl_sync(FM, Br1[q], kk), b1b = __shfl_sync(FM, Br1[q], kk+1);
      float b2a = __shfl_sync(FM, Br2[q], kk), b2b = __shfl_sync(FM, Br2[q], kk+1);
      float b3a = __shfl_sync(FM, Br3[q], kk), b3b = __shfl_sync(FM, Br3[q], kk+1);
      ull wva = Wsu[(q*32 + kk)*32 + lane];
      ull wvb = Wsu[(q*32 + kk + 1)*32 + lane];
      FFMA2(acc0, packf2(b0a, b0a), wva, acc0);
      FFMA2(acc1, packf2(b1a, b1a), wva, acc1);
      FFMA2(acc2, packf2(b2a, b2a), wva, acc2);
      FFMA2(acc3, packf2(b3a, b3a), wva, acc3);
      FFMA2(acc0, packf2(b0b, b0b), wvb, acc0);
      FFMA2(acc1, packf2(b1b, b1b), wvb, acc1);
      FFMA2(acc2, packf2(b2b, b2b), wvb, acc2);
      FFMA2(acc3, packf2(b3b, b3b), wvb, acc3);
    }
  }
  if (nn[0] >= 0) ((ull*)(d_h1 + nn[0]*64))[lane] = acc0;
  if (nn[1] >= 0) ((ull*)(d_h1 + nn[1]*64))[lane] = acc1;
  if (nn[2] >= 0) ((ull*)(d_h1 + nn[2]*64))[lane] = acc2;
  if (nn[3] >= 0) ((ull*)(d_h1 + nn[3]*64))[lane] = acc3;
}

// ---------------- fused: dB0 tile (smem) + layer-0 backward; cleans dh1+deg -------
#define BWD0_SMEM (64*264*4 + 32*66*4 + 32*256*4 + 128)
__global__ void k_bwd0(const float* __restrict__ Wprod, const float* __restrict__ Wemb,
                       const float* __restrict__ Wrad, float* __restrict__ out){
  extern __shared__ float sm[];
  float* Wt  = sm;                        // [c][f] 64 x 264
  float* dhs = sm + 64*264;               // [node][c] 32 x 66
  float* dBs = sm + 64*264 + 32*66;       // [node][f] 32 x 256
  int* nids  = (int*)(sm + 64*264 + 32*66 + 32*256);
  int base = blockIdx.x*32;
  if (base >= d_elptr[NELEM]) return;
  int el = 0;
  #pragma unroll
  for (int e = 1; e < NELEM; e++) if (d_elptr[e] <= base) el = e;
  int tid = threadIdx.x;   // 256
  const float* W = Wprod + el*16384;
  for (int i = tid; i < 16384; i += 256){
    int f = i >> 6, c = i & 63;
    Wt[c*264 + f] = W[i];
  }
  if (tid < 32) nids[tid] = d_nbyel[base + tid];
  __syncthreads();
#if __CUDA_ARCH__ >= 900
  cudaGridDependencySynchronize();      // weight-load prologue overlapped with gfused1
#endif
  for (int i = tid; i < 32*64; i += 256){
    int k = i >> 6, c = i & 63;
    int nn = nids[k];
    if (nn >= 0){
      dhs[k*66 + c] = d_dh1[nn*64 + c];
      d_dh1[nn*64 + c] = 0.f;             // self-clean for next replay
    } else {
      dhs[k*66 + c] = 0.f;
    }
  }
  __syncthreads();
  {
    int ng = tid >> 4, fg = tid & 15;
    float acc0[16], acc1[16];
    #pragma unroll
    for (int i = 0; i < 16; i++){ acc0[i] = 0.f; acc1[i] = 0.f; }
    #pragma unroll 2
    for (int c = 0; c < 64; c++){
      float dd0 = dhs[(2*ng)*66 + c];
      float dd1 = dhs[(2*ng+1)*66 + c];
      const float4* Wc = (const float4*)(Wt + c*264 + fg*16);
      #pragma unroll
      for (int q = 0; q < 4; q++){
        float4 w = Wc[q];
        acc0[4*q]   += dd0*w.x; acc0[4*q+1] += dd0*w.y; acc0[4*q+2] += dd0*w.z; acc0[4*q+3] += dd0*w.w;
        acc1[4*q]   += dd1*w.x; acc1[4*q+1] += dd1*w.y; acc1[4*q+2] += dd1*w.z; acc1[4*q+3] += dd1*w.w;
      }
    }
    float4* o0 = (float4*)(dBs + (2*ng)*256 + fg*16);
    float4* o1 = (float4*)(dBs + (2*ng+1)*256 + fg*16);
    #pragma unroll
    for (int q = 0; q < 4; q++){
      o0[q] = make_float4(acc0[4*q],acc0[4*q+1],acc0[4*q+2],acc0[4*q+3]);
      o1[q] = make_float4(acc1[4*q],acc1[4*q+1],acc1[4*q+2],acc1[4*q+3]);
    }
  }
  __syncthreads();
  int w = tid >> 5, lane = tid & 31;
  float wr0[8], wr1[8];
  #pragma unroll
  for (int b = 0; b < 8; b++){ wr0[b] = Wrad[b*64+lane]; wr1[b] = Wrad[b*64+32+lane]; }
  for (int q = 0; q < 4; q++){
    int nloc = w*4 + q;
    int nn = nids[nloc];
    if (nn < 0) continue;
    int dg = min(d_deg[nn], CAP);
    if (lane == 0) d_deg[nn] = 0;         // self-clean for next replay
    if (dg == 0) continue;
    const float* dB = dBs + nloc*256;
    const float2* A2 = (const float2*)(d_A + nn*1024);
    float dA0[16], dA1[16];
    #pragma unroll
    for (int lm = 0; lm < 16; lm++){
      int l = (lm == 0) ? 0 : (lm < 4) ? 1 : (lm < 9) ? 2 : 3;
      float2 av = A2[lm*32 + lane];
      dA0[lm] = 2.f*av.x*dB[l*64 + lane];
      dA1[lm] = 2.f*av.y*dB[l*64 + 32 + lane];
    }
    edge_bwd_loop<0>(nn, lane, dg, Wemb, dA0, dA1, wr0, wr1, out + GG);
  }
}

// ---------------- launch ----------------
extern "C" void kernel_launch(void* const* d_in, const int* in_sizes, int n_in,
                              void* d_out, int out_size){
  const float* pos    = (const float*)d_in[0];
  const float* attrs  = (const float*)d_in[1];
  const float* shifts = (const float*)d_in[2];
  const float* Wemb   = (const float*)d_in[3];
  const float* aew    = (const float*)d_in[4];
  const float* Wrad   = (const float*)d_in[5];
  const float* Wprod  = (const float*)d_in[6];
  const float* wread  = (const float*)d_in[7];
  const int*   ei     = (const int*)d_in[8];
  const int*   batch  = (const int*)d_in[9];
  float* out = (float*)d_out;

  static cudaStream_t s2 = nullptr;
  static cudaEvent_t ev0 = nullptr, evM = nullptr;
  if (!s2){
    cudaFuncSetAttribute(k_gemm_h0, cudaFuncAttributeMaxDynamicSharedMemorySize, GH_SMEM);
    cudaFuncSetAttribute(k_bwd0,    cudaFuncAttributeMaxDynamicSharedMemorySize, BWD0_SMEM);
    cudaStreamCreateWithFlags(&s2, cudaStreamNonBlocking);
    cudaEventCreateWithFlags(&ev0, cudaEventDisableTiming);
    cudaEventCreateWithFlags(&evM, cudaEventDisableTiming);
  }

  // fork misc (element grouping + dB1e) — depends only on inputs
  cudaEventRecord(ev0, 0);
  cudaStreamWaitEvent(s2, ev0, 0);
  k_misc<<<1 + NELEM, 256, 0, s2>>>(attrs, Wprod, wread);
  cudaEventRecord(evM, s2);

  k_geom<<<256 + (OUTSZ + 255)/256, 256>>>(pos, shifts, ei, attrs, out);

  cudaLaunchAttribute pdl[1];
  pdl[0].id = cudaLaunchAttributeProgrammaticStreamSerialization;
  pdl[0].val.programmaticStreamSerializationAllowed = 1;

  {
    cudaLaunchConfig_t cfg = {};
    cfg.gridDim = dim3(NN/4); cfg.blockDim = dim3(128);
    cfg.dynamicSmemBytes = 0; cfg.stream = 0;
    cfg.attrs = pdl; cfg.numAttrs = 1;
    cudaLaunchKernelEx(&cfg, k_gather0, Wemb, Wrad);
  }
  cudaStreamWaitEvent(0, evM, 0);
  {
    cudaLaunchConfig_t cfg = {};
    cfg.gridDim = dim3(NTILES); cfg.blockDim = dim3(256);
    cfg.dynamicSmemBytes = GH_SMEM; cfg.stream = 0;
    cfg.attrs = pdl; cfg.numAttrs = 1;
    cudaLaunchKernelEx(&cfg, k_gemm_h0, Wprod);
  }
  {
    cudaLaunchConfig_t cfg = {};
    cfg.gridDim = dim3(NN/4); cfg.blockDim = dim3(128);
    cfg.dynamicSmemBytes = 0; cfg.stream = 0;
    cfg.attrs = pdl; cfg.numAttrs = 1;
    cudaLaunchKernelEx(&cfg, k_gfused1, Wemb, Wrad + 512, aew, batch, out);
  }
  {
    cudaLaunchConfig_t cfg = {};
    cfg.gridDim = dim3(NTILES); cfg.blockDim = dim3(256);
    cfg.dynamicSmemBytes = BWD0_SMEM; cfg.stream = 0;
    cfg.attrs = pdl; cfg.numAttrs = 1;
    cudaLaunchKernelEx(&cfg, k_bwd0, Wprod, Wemb, Wrad, out);
  }
}